// round 1
// baseline (speedup 1.0000x reference)
#include <cuda_runtime.h>
#include <math.h>

#define BATCH 2
#define SEQ   2048
#define DM    1024
#define NH    16
#define DEPTH 64
#define MTOT  (BATCH*SEQ)   // 4096

// Scratch: head-split activations [B, H, S, depth] = 4M floats each (16 MB)
__device__ float g_Q[BATCH*NH*SEQ*DEPTH];
__device__ float g_K[BATCH*NH*SEQ*DEPTH];
__device__ float g_V[BATCH*NH*SEQ*DEPTH];
__device__ float g_O[BATCH*NH*SEQ*DEPTH];

// ---------------------------------------------------------------------------
// GEMM: C[m,n] = sum_k A[m,k] * W[n,k] + bias[n]   (torch Linear: x @ W.T + b)
// A: [4096,1024] row-major (or gathered from head-split g_O when GATHER_A)
// W: [1024,1024] row-major
// SPLIT_OUT: write C into head-split layout [B,H,S,depth] instead of [M,N]
// Tiling: 128x128 block, BK=16, 256 threads, 8x8 per-thread microtile.
// ---------------------------------------------------------------------------
template<bool GATHER_A, bool SPLIT_OUT>
__global__ __launch_bounds__(256)
void gemm_kernel(const float* __restrict__ A,
                 const float* __restrict__ W,
                 const float* __restrict__ bias,
                 float* __restrict__ C)
{
    constexpr int BM = 128, BN = 128, BK = 16;
    __shared__ float As[BK][BM + 4];
    __shared__ float Bs[BK][BN + 4];

    const int bm  = blockIdx.x * BM;
    const int bn  = blockIdx.y * BN;
    const int tid = threadIdx.x;
    const int tx  = tid & 15;    // n-dim thread coord
    const int ty  = tid >> 4;    // m-dim thread coord

    float acc[8][8];
#pragma unroll
    for (int i = 0; i < 8; i++)
#pragma unroll
        for (int j = 0; j < 8; j++) acc[i][j] = 0.f;

    for (int k0 = 0; k0 < DM; k0 += BK) {
        // Each tile is 128 rows x 16 cols = 512 float4 loads; 2 per thread.
#pragma unroll
        for (int l = 0; l < 2; l++) {
            int idx = tid + l * 256;        // 0..511
            int row = idx >> 2;             // 0..127
            int c4  = (idx & 3) << 2;       // 0,4,8,12
            int m   = bm + row;
            int k   = k0 + c4;

            float4 va;
            if (GATHER_A) {
                // A[m,k] comes from head-split g_O: [B,H,S,depth]
                int b = m >> 11, s = m & 2047;
                int h = k >> 6,  d = k & 63;
                va = *(const float4*)(A + ((((b << 4) + h) * SEQ + s) << 6) + d);
            } else {
                va = *(const float4*)(A + m * DM + k);
            }
            As[c4 + 0][row] = va.x; As[c4 + 1][row] = va.y;
            As[c4 + 2][row] = va.z; As[c4 + 3][row] = va.w;

            float4 vw = *(const float4*)(W + (bn + row) * DM + k0 + c4);
            Bs[c4 + 0][row] = vw.x; Bs[c4 + 1][row] = vw.y;
            Bs[c4 + 2][row] = vw.z; Bs[c4 + 3][row] = vw.w;
        }
        __syncthreads();

#pragma unroll
        for (int k = 0; k < BK; k++) {
            float a[8], b[8];
            *(float4*)(a)     = *(const float4*)&As[k][ty * 8];
            *(float4*)(a + 4) = *(const float4*)&As[k][ty * 8 + 4];
            *(float4*)(b)     = *(const float4*)&Bs[k][tx * 8];
            *(float4*)(b + 4) = *(const float4*)&Bs[k][tx * 8 + 4];
#pragma unroll
            for (int i = 0; i < 8; i++)
#pragma unroll
                for (int j = 0; j < 8; j++)
                    acc[i][j] = fmaf(a[i], b[j], acc[i][j]);
        }
        __syncthreads();
    }

    // Epilogue: add bias, write out
#pragma unroll
    for (int i = 0; i < 8; i++) {
        int m = bm + ty * 8 + i;
        int b = m >> 11, s = m & 2047;
#pragma unroll
        for (int j = 0; j < 8; j++) {
            int n = bn + tx * 8 + j;
            float val = acc[i][j] + bias[n];
            if (SPLIT_OUT) {
                int h = n >> 6, d = n & 63;
                C[((((b << 4) + h) * SEQ + s) << 6) + d] = val;
            } else {
                C[m * DM + n] = val;
            }
        }
    }
}

// ---------------------------------------------------------------------------
// Fused flash attention (fp32): per block, one (b,h) and a 64-row Q tile.
// Loops over 32 key tiles of 64 rows; online softmax; O accum in registers.
// 256 threads; each owns a 4x4 microtile of the 64x64 score/output tiles.
// Scale 1/sqrt(64)=0.125 folded into the Q load (exact, power of two).
// ---------------------------------------------------------------------------
__global__ __launch_bounds__(256)
void attn_kernel(const float* __restrict__ Q, const float* __restrict__ K,
                 const float* __restrict__ V, float* __restrict__ O)
{
    constexpr int PAD = 68;  // 64 + 4 floats; keeps rows 16B aligned, kills conflicts
    extern __shared__ float sm[];
    float (*Qs)[PAD] = (float(*)[PAD])(sm);
    float (*Ks)[PAD] = (float(*)[PAD])(sm + 64 * PAD);
    float (*Vs)[PAD] = (float(*)[PAD])(sm + 2 * 64 * PAD);
    float (*Ps)[PAD] = (float(*)[PAD])(sm + 3 * 64 * PAD);

    const int qt = blockIdx.x;                    // q tile, 0..31
    const int bh = blockIdx.z * NH + blockIdx.y;  // (b,h) flat
    const float* Qp = Q + (bh * SEQ + qt * 64) * DEPTH;
    const float* Kp = K + bh * SEQ * DEPTH;
    const float* Vp = V + bh * SEQ * DEPTH;
    float*       Op = O + (bh * SEQ + qt * 64) * DEPTH;

    const int tid = threadIdx.x;
    const int tx  = tid & 15;       // col group (keys / depth)
    const int ty  = tid >> 4;       // row group (queries)
    const int r0  = ty * 4;
    const int c0  = tx * 4;

    // Load + scale Q tile (64x64 = 1024 float4, 4 per thread)
    for (int l = tid; l < 64 * 16; l += 256) {
        int row = l >> 4, c4 = (l & 15) << 2;
        float4 v = *(const float4*)(Qp + row * DEPTH + c4);
        v.x *= 0.125f; v.y *= 0.125f; v.z *= 0.125f; v.w *= 0.125f;
        *(float4*)&Qs[row][c4] = v;
    }

    float acc[4][4];
    float m_i[4], l_i[4];
#pragma unroll
    for (int r = 0; r < 4; r++) {
        m_i[r] = -1e30f; l_i[r] = 0.f;
#pragma unroll
        for (int c = 0; c < 4; c++) acc[r][c] = 0.f;
    }

    for (int kt = 0; kt < SEQ / 64; kt++) {
        __syncthreads();  // prior-iter consumers of Ks/Vs/Ps done (and Qs visible, kt=0)

        const float* Kt = Kp + kt * 64 * DEPTH;
        const float* Vt = Vp + kt * 64 * DEPTH;
        for (int l = tid; l < 64 * 16; l += 256) {
            int row = l >> 4, c4 = (l & 15) << 2;
            *(float4*)&Ks[row][c4] = *(const float4*)(Kt + row * DEPTH + c4);
            *(float4*)&Vs[row][c4] = *(const float4*)(Vt + row * DEPTH + c4);
        }
        __syncthreads();

        // ---- scores: s = (Q/8) . K^T, 4x4 per thread ----
        float s[4][4];
#pragma unroll
        for (int r = 0; r < 4; r++)
#pragma unroll
            for (int c = 0; c < 4; c++) s[r][c] = 0.f;

#pragma unroll
        for (int d4 = 0; d4 < DEPTH; d4 += 4) {
            float qr[4][4], kr[4][4];
#pragma unroll
            for (int r = 0; r < 4; r++)
                *(float4*)qr[r] = *(const float4*)&Qs[r0 + r][d4];
#pragma unroll
            for (int c = 0; c < 4; c++)
                *(float4*)kr[c] = *(const float4*)&Ks[c0 + c][d4];
#pragma unroll
            for (int r = 0; r < 4; r++)
#pragma unroll
                for (int c = 0; c < 4; c++)
#pragma unroll
                    for (int dd = 0; dd < 4; dd++)
                        s[r][c] = fmaf(qr[r][dd], kr[c][dd], s[r][c]);
        }

        // ---- online softmax (rows owned by 16-lane groups: same ty) ----
#pragma unroll
        for (int r = 0; r < 4; r++) {
            float mx = fmaxf(fmaxf(s[r][0], s[r][1]), fmaxf(s[r][2], s[r][3]));
#pragma unroll
            for (int off = 8; off >= 1; off >>= 1)
                mx = fmaxf(mx, __shfl_xor_sync(0xffffffffu, mx, off));
            float mnew = fmaxf(m_i[r], mx);
            float corr = __expf(m_i[r] - mnew);
            m_i[r] = mnew;

            float p[4], rs = 0.f;
#pragma unroll
            for (int c = 0; c < 4; c++) { p[c] = __expf(s[r][c] - mnew); rs += p[c]; }
#pragma unroll
            for (int off = 8; off >= 1; off >>= 1)
                rs += __shfl_xor_sync(0xffffffffu, rs, off);
            l_i[r] = l_i[r] * corr + rs;
#pragma unroll
            for (int c = 0; c < 4; c++) acc[r][c] *= corr;
            *(float4*)&Ps[r0 + r][c0] = make_float4(p[0], p[1], p[2], p[3]);
        }
        __syncthreads();

        // ---- O += P @ V, 4x4 per thread, thread cols = depth slice c0..c0+3 ----
#pragma unroll
        for (int j4 = 0; j4 < 64; j4 += 4) {
            float pr[4][4], vr[4][4];
#pragma unroll
            for (int r = 0; r < 4; r++)
                *(float4*)pr[r] = *(const float4*)&Ps[r0 + r][j4];
#pragma unroll
            for (int jj = 0; jj < 4; jj++)
                *(float4*)vr[jj] = *(const float4*)&Vs[j4 + jj][c0];
#pragma unroll
            for (int r = 0; r < 4; r++)
#pragma unroll
                for (int c = 0; c < 4; c++)
#pragma unroll
                    for (int jj = 0; jj < 4; jj++)
                        acc[r][c] = fmaf(pr[r][jj], vr[jj][c], acc[r][c]);
        }
    }

    // ---- epilogue: normalize and store ----
#pragma unroll
    for (int r = 0; r < 4; r++) {
        float inv = 1.f / l_i[r];
        float4 o = make_float4(acc[r][0] * inv, acc[r][1] * inv,
                               acc[r][2] * inv, acc[r][3] * inv);
        *(float4*)(Op + (r0 + r) * DEPTH + c0) = o;
    }
}

// ---------------------------------------------------------------------------
extern "C" void kernel_launch(void* const* d_in, const int* in_sizes, int n_in,
                              void* d_out, int out_size)
{
    const float* q  = (const float*)d_in[0];
    const float* k  = (const float*)d_in[1];
    const float* v  = (const float*)d_in[2];
    const float* wq = (const float*)d_in[3];
    const float* bq = (const float*)d_in[4];
    const float* wk = (const float*)d_in[5];
    const float* bk = (const float*)d_in[6];
    const float* wv = (const float*)d_in[7];
    const float* bv = (const float*)d_in[8];
    const float* wo = (const float*)d_in[9];
    const float* bo = (const float*)d_in[10];
    float* out = (float*)d_out;

    float *gQ, *gK, *gV, *gO;
    cudaGetSymbolAddress((void**)&gQ, g_Q);
    cudaGetSymbolAddress((void**)&gK, g_K);
    cudaGetSymbolAddress((void**)&gV, g_V);
    cudaGetSymbolAddress((void**)&gO, g_O);

    dim3 gproj(MTOT / 128, DM / 128);  // (32, 8)

    // QKV projections -> head-split scratch
    gemm_kernel<false, true><<<gproj, 256>>>(q, wq, bq, gQ);
    gemm_kernel<false, true><<<gproj, 256>>>(k, wk, bk, gK);
    gemm_kernel<false, true><<<gproj, 256>>>(v, wv, bv, gV);

    // Fused flash attention
    size_t smem = 4 * 64 * 68 * sizeof(float);  // 69632 B
    cudaFuncSetAttribute(attn_kernel, cudaFuncAttributeMaxDynamicSharedMemorySize,
                         (int)smem);
    attn_kernel<<<dim3(SEQ / 64, NH, BATCH), 256, smem>>>(gQ, gK, gV, gO);

    // Output projection (gathers head-split O as the merged context)
    gemm_kernel<true, false><<<gproj, 256>>>(gO, wo, bo, out);
}

// round 3
// speedup vs baseline: 1.2954x; 1.2954x over previous
#include <cuda_runtime.h>
#include <cuda_bf16.h>
#include <cstdint>
#include <math.h>

#define BATCH 2
#define SEQ   2048
#define DM    1024
#define NH    16
#define DEPTH 64
#define MTOT  (BATCH*SEQ)   // 4096

// Scratch: head-split activations [B, H, S, depth] (16 MB each)
__device__ float g_Q[BATCH*NH*SEQ*DEPTH];
__device__ float g_K[BATCH*NH*SEQ*DEPTH];
__device__ float g_V[BATCH*NH*SEQ*DEPTH];
__device__ float g_O[BATCH*NH*SEQ*DEPTH];

// ===========================================================================
// helpers
// ===========================================================================
__device__ __forceinline__ uint32_t smem_u32(const void* p) {
    uint32_t a;
    asm("{ .reg .u64 t; cvta.to.shared.u64 t, %1; cvt.u32.u64 %0, t; }"
        : "=r"(a) : "l"(p));
    return a;
}

__device__ __forceinline__ uint32_t pack_bf16(float x, float y) {
    uint32_t lo = __bfloat16_as_ushort(__float2bfloat16(x));
    uint32_t hi = __bfloat16_as_ushort(__float2bfloat16(y));
    return lo | (hi << 16);
}

#define LDSM4(R, addr) \
    asm volatile("ldmatrix.sync.aligned.m8n8.x4.shared.b16 {%0,%1,%2,%3}, [%4];" \
        : "=r"((R)[0]), "=r"((R)[1]), "=r"((R)[2]), "=r"((R)[3]) : "r"(addr))

#define MMA16816(D, A, B0, B1) \
    asm volatile("mma.sync.aligned.m16n8k16.row.col.f32.bf16.bf16.f32 " \
        "{%0,%1,%2,%3}, {%4,%5,%6,%7}, {%8,%9}, {%0,%1,%2,%3};" \
        : "+f"((D)[0]), "+f"((D)[1]), "+f"((D)[2]), "+f"((D)[3]) \
        : "r"((A)[0]), "r"((A)[1]), "r"((A)[2]), "r"((A)[3]), "r"(B0), "r"(B1))

// ===========================================================================
// Split-bf16 tensor-core GEMM via mma.sync (HMMA):
//   C[m,n] = sum_k A[m,k] * W[n,k] + bias[n]
// CTA tile 128x128, BK=32, 256 threads = 8 warps (2m x 4n), warp tile 64x32.
// A = Ahi + Alo (bf16), W = Bhi + Blo; D += Ah*Bh + Ah*Bl + Al*Bh (fp32 acc).
// Smem: 4 matrices of 128 rows x 32 bf16, row stride 80B (ldmatrix
// conflict-free: r*80 mod 128 covers all eight 16B lines).
// ===========================================================================
#define ROWB 80                        // bytes per smem row
#define MAT_BYTES (128 * ROWB)         // 10240
#define OFF_AHI 0
#define OFF_ALO (MAT_BYTES)
#define OFF_BHI (2 * MAT_BYTES)
#define OFF_BLO (3 * MAT_BYTES)
#define GEMM_SMEM (4 * MAT_BYTES)      // 40960

template<bool GATHER_A, bool SPLIT_OUT>
__global__ __launch_bounds__(256)
void gemm_mma(const float* __restrict__ A, const float* __restrict__ W,
              const float* __restrict__ bias, float* __restrict__ C)
{
    extern __shared__ char smem[];
    const uint32_t sb = smem_u32(smem);

    const int tid = threadIdx.x;
    const int wid = tid >> 5, lid = tid & 31;
    const int warp_m = wid >> 2;       // 0..1
    const int warp_n = wid & 3;        // 0..3
    const int bm = blockIdx.x * 128, bn = blockIdx.y * 128;

    // ldmatrix per-lane address pieces
    const int grp = lid >> 3, r = lid & 7;
    const uint32_t a_base = sb + OFF_AHI
        + (uint32_t)(warp_m * 64 + ((grp & 1) << 3) + r) * ROWB
        + (uint32_t)(((grp >> 1) & 1) << 4);           // k8*2 bytes
    const uint32_t b_base = sb + OFF_BHI
        + (uint32_t)(warp_n * 32 + (((grp >> 1) & 1) << 3) + r) * ROWB
        + (uint32_t)((grp & 1) << 4);

    float acc[4][4][4];
#pragma unroll
    for (int i = 0; i < 4; i++)
#pragma unroll
        for (int j = 0; j < 4; j++)
#pragma unroll
            for (int e = 0; e < 4; e++) acc[i][j][e] = 0.f;

    for (int it = 0; it < DM / 32; it++) {
        const int k0 = it * 32;
        __syncthreads();   // previous iter's ldmatrix reads done

        // ---- load 128x32 fp32 of A and W; split to bf16 hi/lo in smem ----
#pragma unroll
        for (int l = 0; l < 4; l++) {
            int idx = tid + l * 256;       // 0..1023
            int row = idx >> 3;            // 0..127
            int cf  = (idx & 7) << 2;      // float col 0..28
            uint32_t soff = (uint32_t)row * ROWB + (uint32_t)cf * 2;

            float4 va;
            if (GATHER_A) {
                int m = bm + row;
                int b = m >> 11, s = m & 2047;
                int h = it >> 1, dl = ((it & 1) << 5) + cf;
                va = *(const float4*)(A + ((((b << 4) + h) * SEQ + s) << 6) + dl);
            } else {
                va = *(const float4*)(A + (size_t)(bm + row) * DM + k0 + cf);
            }
            float hx = __bfloat162float(__float2bfloat16(va.x));
            float hy = __bfloat162float(__float2bfloat16(va.y));
            float hz = __bfloat162float(__float2bfloat16(va.z));
            float hw = __bfloat162float(__float2bfloat16(va.w));
            *(uint2*)(smem + OFF_AHI + soff) =
                make_uint2(pack_bf16(va.x, va.y), pack_bf16(va.z, va.w));
            *(uint2*)(smem + OFF_ALO + soff) =
                make_uint2(pack_bf16(va.x - hx, va.y - hy),
                           pack_bf16(va.z - hz, va.w - hw));

            float4 vw = *(const float4*)(W + (size_t)(bn + row) * DM + k0 + cf);
            hx = __bfloat162float(__float2bfloat16(vw.x));
            hy = __bfloat162float(__float2bfloat16(vw.y));
            hz = __bfloat162float(__float2bfloat16(vw.z));
            hw = __bfloat162float(__float2bfloat16(vw.w));
            *(uint2*)(smem + OFF_BHI + soff) =
                make_uint2(pack_bf16(vw.x, vw.y), pack_bf16(vw.z, vw.w));
            *(uint2*)(smem + OFF_BLO + soff) =
                make_uint2(pack_bf16(vw.x - hx, vw.y - hy),
                           pack_bf16(vw.z - hz, vw.w - hw));
        }
        __syncthreads();

        // ---- 2 x k16 steps ----
#pragma unroll
        for (int ks = 0; ks < 2; ks++) {
            const uint32_t offk = (uint32_t)ks * 32;
            uint32_t ah[4][4], al[4][4], bh[2][4], bl[2][4];
#pragma unroll
            for (int fm = 0; fm < 4; fm++) {
                LDSM4(ah[fm], a_base + fm * (16 * ROWB) + offk);
                LDSM4(al[fm], a_base + (OFF_ALO - OFF_AHI) + fm * (16 * ROWB) + offk);
            }
#pragma unroll
            for (int p = 0; p < 2; p++) {
                LDSM4(bh[p], b_base + p * (16 * ROWB) + offk);
                LDSM4(bl[p], b_base + (OFF_BLO - OFF_BHI) + p * (16 * ROWB) + offk);
            }
#pragma unroll
            for (int fm = 0; fm < 4; fm++)
#pragma unroll
                for (int fn = 0; fn < 4; fn++) {
                    const int p = fn >> 1, o = (fn & 1) << 1;
                    MMA16816(acc[fm][fn], ah[fm], bh[p][o], bh[p][o + 1]);
                    MMA16816(acc[fm][fn], ah[fm], bl[p][o], bl[p][o + 1]);
                    MMA16816(acc[fm][fn], al[fm], bh[p][o], bh[p][o + 1]);
                }
        }
    }

    // ---- epilogue: bias + store straight from fragments ----
    const int qrow = lid >> 2;
    const int qcol = (lid & 3) << 1;
#pragma unroll
    for (int fm = 0; fm < 4; fm++) {
        int m1 = bm + warp_m * 64 + fm * 16 + qrow;
        int m2 = m1 + 8;
#pragma unroll
        for (int fn = 0; fn < 4; fn++) {
            int n = bn + warp_n * 32 + fn * 8 + qcol;
            float2 bb = *(const float2*)(bias + n);
            float2 v1 = make_float2(acc[fm][fn][0] + bb.x, acc[fm][fn][1] + bb.y);
            float2 v2 = make_float2(acc[fm][fn][2] + bb.x, acc[fm][fn][3] + bb.y);
            if (SPLIT_OUT) {
                int h = n >> 6, dl = n & 63;
                int b1 = m1 >> 11, s1 = m1 & 2047;
                int b2 = m2 >> 11, s2 = m2 & 2047;
                *(float2*)(C + ((((b1 << 4) + h) * SEQ + s1) << 6) + dl) = v1;
                *(float2*)(C + ((((b2 << 4) + h) * SEQ + s2) << 6) + dl) = v2;
            } else {
                *(float2*)(C + (size_t)m1 * DM + n) = v1;
                *(float2*)(C + (size_t)m2 * DM + n) = v2;
            }
        }
    }
}

// ---------------------------------------------------------------------------
// Fused flash attention (fp32) — unchanged (known good from round 1).
// ---------------------------------------------------------------------------
__global__ __launch_bounds__(256)
void attn_kernel(const float* __restrict__ Q, const float* __restrict__ K,
                 const float* __restrict__ V, float* __restrict__ O)
{
    constexpr int PAD = 68;
    extern __shared__ float sm[];
    float (*Qs)[PAD] = (float(*)[PAD])(sm);
    float (*Ks)[PAD] = (float(*)[PAD])(sm + 64 * PAD);
    float (*Vs)[PAD] = (float(*)[PAD])(sm + 2 * 64 * PAD);
    float (*Ps)[PAD] = (float(*)[PAD])(sm + 3 * 64 * PAD);

    const int qt = blockIdx.x;
    const int bh = blockIdx.z * NH + blockIdx.y;
    const float* Qp = Q + (bh * SEQ + qt * 64) * DEPTH;
    const float* Kp = K + bh * SEQ * DEPTH;
    const float* Vp = V + bh * SEQ * DEPTH;
    float*       Op = O + (bh * SEQ + qt * 64) * DEPTH;

    const int tid = threadIdx.x;
    const int tx  = tid & 15;
    const int ty  = tid >> 4;
    const int r0  = ty * 4;
    const int c0  = tx * 4;

    for (int l = tid; l < 64 * 16; l += 256) {
        int row = l >> 4, c4 = (l & 15) << 2;
        float4 v = *(const float4*)(Qp + row * DEPTH + c4);
        v.x *= 0.125f; v.y *= 0.125f; v.z *= 0.125f; v.w *= 0.125f;
        *(float4*)&Qs[row][c4] = v;
    }

    float acc[4][4];
    float m_i[4], l_i[4];
#pragma unroll
    for (int r = 0; r < 4; r++) {
        m_i[r] = -1e30f; l_i[r] = 0.f;
#pragma unroll
        for (int c = 0; c < 4; c++) acc[r][c] = 0.f;
    }

    for (int kt = 0; kt < SEQ / 64; kt++) {
        __syncthreads();

        const float* Kt = Kp + kt * 64 * DEPTH;
        const float* Vt = Vp + kt * 64 * DEPTH;
        for (int l = tid; l < 64 * 16; l += 256) {
            int row = l >> 4, c4 = (l & 15) << 2;
            *(float4*)&Ks[row][c4] = *(const float4*)(Kt + row * DEPTH + c4);
            *(float4*)&Vs[row][c4] = *(const float4*)(Vt + row * DEPTH + c4);
        }
        __syncthreads();

        float s[4][4];
#pragma unroll
        for (int r = 0; r < 4; r++)
#pragma unroll
            for (int c = 0; c < 4; c++) s[r][c] = 0.f;

#pragma unroll
        for (int d4 = 0; d4 < DEPTH; d4 += 4) {
            float qr[4][4], kr[4][4];
#pragma unroll
            for (int r = 0; r < 4; r++)
                *(float4*)qr[r] = *(const float4*)&Qs[r0 + r][d4];
#pragma unroll
            for (int c = 0; c < 4; c++)
                *(float4*)kr[c] = *(const float4*)&Ks[c0 + c][d4];
#pragma unroll
            for (int r = 0; r < 4; r++)
#pragma unroll
                for (int c = 0; c < 4; c++)
#pragma unroll
                    for (int dd = 0; dd < 4; dd++)
                        s[r][c] = fmaf(qr[r][dd], kr[c][dd], s[r][c]);
        }

#pragma unroll
        for (int r = 0; r < 4; r++) {
            float mx = fmaxf(fmaxf(s[r][0], s[r][1]), fmaxf(s[r][2], s[r][3]));
#pragma unroll
            for (int off = 8; off >= 1; off >>= 1)
                mx = fmaxf(mx, __shfl_xor_sync(0xffffffffu, mx, off));
            float mnew = fmaxf(m_i[r], mx);
            float corr = __expf(m_i[r] - mnew);
            m_i[r] = mnew;

            float p[4], rs = 0.f;
#pragma unroll
            for (int c = 0; c < 4; c++) { p[c] = __expf(s[r][c] - mnew); rs += p[c]; }
#pragma unroll
            for (int off = 8; off >= 1; off >>= 1)
                rs += __shfl_xor_sync(0xffffffffu, rs, off);
            l_i[r] = l_i[r] * corr + rs;
#pragma unroll
            for (int c = 0; c < 4; c++) acc[r][c] *= corr;
            *(float4*)&Ps[r0 + r][c0] = make_float4(p[0], p[1], p[2], p[3]);
        }
        __syncthreads();

#pragma unroll
        for (int j4 = 0; j4 < 64; j4 += 4) {
            float pr[4][4], vr[4][4];
#pragma unroll
            for (int r = 0; r < 4; r++)
                *(float4*)pr[r] = *(const float4*)&Ps[r0 + r][j4];
#pragma unroll
            for (int jj = 0; jj < 4; jj++)
                *(float4*)vr[jj] = *(const float4*)&Vs[j4 + jj][c0];
#pragma unroll
            for (int r = 0; r < 4; r++)
#pragma unroll
                for (int c = 0; c < 4; c++)
#pragma unroll
                    for (int jj = 0; jj < 4; jj++)
                        acc[r][c] = fmaf(pr[r][jj], vr[jj][c], acc[r][c]);
        }
    }

#pragma unroll
    for (int r = 0; r < 4; r++) {
        float inv = 1.f / l_i[r];
        float4 o = make_float4(acc[r][0] * inv, acc[r][1] * inv,
                               acc[r][2] * inv, acc[r][3] * inv);
        *(float4*)(Op + (r0 + r) * DEPTH + c0) = o;
    }
}

// ---------------------------------------------------------------------------
extern "C" void kernel_launch(void* const* d_in, const int* in_sizes, int n_in,
                              void* d_out, int out_size)
{
    const float* q  = (const float*)d_in[0];
    const float* k  = (const float*)d_in[1];
    const float* v  = (const float*)d_in[2];
    const float* wq = (const float*)d_in[3];
    const float* bq = (const float*)d_in[4];
    const float* wk = (const float*)d_in[5];
    const float* bk = (const float*)d_in[6];
    const float* wv = (const float*)d_in[7];
    const float* bv = (const float*)d_in[8];
    const float* wo = (const float*)d_in[9];
    const float* bo = (const float*)d_in[10];
    float* out = (float*)d_out;

    float *gQ, *gK, *gV, *gO;
    cudaGetSymbolAddress((void**)&gQ, g_Q);
    cudaGetSymbolAddress((void**)&gK, g_K);
    cudaGetSymbolAddress((void**)&gV, g_V);
    cudaGetSymbolAddress((void**)&gO, g_O);

    dim3 gproj(MTOT / 128, DM / 128);  // (32, 8)

    gemm_mma<false, true><<<gproj, 256, GEMM_SMEM>>>(q, wq, bq, gQ);
    gemm_mma<false, true><<<gproj, 256, GEMM_SMEM>>>(k, wk, bk, gK);
    gemm_mma<false, true><<<gproj, 256, GEMM_SMEM>>>(v, wv, bv, gV);

    size_t smem = 4 * 64 * 68 * sizeof(float);  // 69632 B
    cudaFuncSetAttribute(attn_kernel, cudaFuncAttributeMaxDynamicSharedMemorySize,
                         (int)smem);
    attn_kernel<<<dim3(SEQ / 64, NH, BATCH), 256, smem>>>(gQ, gK, gV, gO);

    gemm_mma<true, false><<<gproj, 256, GEMM_SMEM>>>(gO, wo, bo, out);
}

// round 4
// speedup vs baseline: 3.1509x; 2.4323x over previous
#include <cuda_runtime.h>
#include <cuda_bf16.h>
#include <cstdint>
#include <math.h>

#define BATCH 2
#define SEQ   2048
#define DM    1024
#define NH    16
#define DEPTH 64
#define MTOT  (BATCH*SEQ)   // 4096

// Scratch: head-split activations [B, H, S, depth] (16 MB each)
__device__ float g_Q[BATCH*NH*SEQ*DEPTH];
__device__ float g_K[BATCH*NH*SEQ*DEPTH];
__device__ float g_V[BATCH*NH*SEQ*DEPTH];
__device__ float g_O[BATCH*NH*SEQ*DEPTH];

// ===========================================================================
// helpers
// ===========================================================================
__device__ __forceinline__ uint32_t smem_u32(const void* p) {
    uint32_t a;
    asm("{ .reg .u64 t; cvta.to.shared.u64 t, %1; cvt.u32.u64 %0, t; }"
        : "=r"(a) : "l"(p));
    return a;
}
__device__ __forceinline__ uint32_t pack_bf16(float x, float y) {
    uint32_t lo = __bfloat16_as_ushort(__float2bfloat16(x));
    uint32_t hi = __bfloat16_as_ushort(__float2bfloat16(y));
    return lo | (hi << 16);
}
__device__ __forceinline__ float rb(float x) {   // round to bf16, back to f32
    return __bfloat162float(__float2bfloat16(x));
}

#define LDSM4(R, addr) \
    asm volatile("ldmatrix.sync.aligned.m8n8.x4.shared.b16 {%0,%1,%2,%3}, [%4];" \
        : "=r"((R)[0]), "=r"((R)[1]), "=r"((R)[2]), "=r"((R)[3]) : "r"(addr))

#define MMA16816(D, A, B0, B1) \
    asm volatile("mma.sync.aligned.m16n8k16.row.col.f32.bf16.bf16.f32 " \
        "{%0,%1,%2,%3}, {%4,%5,%6,%7}, {%8,%9}, {%0,%1,%2,%3};" \
        : "+f"((D)[0]), "+f"((D)[1]), "+f"((D)[2]), "+f"((D)[3]) \
        : "r"((A)[0]), "r"((A)[1]), "r"((A)[2]), "r"((A)[3]), "r"(B0), "r"(B1))

// ===========================================================================
// Split-bf16 tensor-core GEMM (unchanged, validated round 3)
// ===========================================================================
#define ROWB 80
#define MAT_BYTES (128 * ROWB)
#define OFF_AHI 0
#define OFF_ALO (MAT_BYTES)
#define OFF_BHI (2 * MAT_BYTES)
#define OFF_BLO (3 * MAT_BYTES)
#define GEMM_SMEM (4 * MAT_BYTES)

template<bool GATHER_A, bool SPLIT_OUT>
__global__ __launch_bounds__(256)
void gemm_mma(const float* __restrict__ A, const float* __restrict__ W,
              const float* __restrict__ bias, float* __restrict__ C)
{
    extern __shared__ char smem[];
    const uint32_t sb = smem_u32(smem);

    const int tid = threadIdx.x;
    const int wid = tid >> 5, lid = tid & 31;
    const int warp_m = wid >> 2;
    const int warp_n = wid & 3;
    const int bm = blockIdx.x * 128, bn = blockIdx.y * 128;

    const int grp = lid >> 3, r = lid & 7;
    const uint32_t a_base = sb + OFF_AHI
        + (uint32_t)(warp_m * 64 + ((grp & 1) << 3) + r) * ROWB
        + (uint32_t)(((grp >> 1) & 1) << 4);
    const uint32_t b_base = sb + OFF_BHI
        + (uint32_t)(warp_n * 32 + (((grp >> 1) & 1) << 3) + r) * ROWB
        + (uint32_t)((grp & 1) << 4);

    float acc[4][4][4];
#pragma unroll
    for (int i = 0; i < 4; i++)
#pragma unroll
        for (int j = 0; j < 4; j++)
#pragma unroll
            for (int e = 0; e < 4; e++) acc[i][j][e] = 0.f;

    for (int it = 0; it < DM / 32; it++) {
        const int k0 = it * 32;
        __syncthreads();

#pragma unroll
        for (int l = 0; l < 4; l++) {
            int idx = tid + l * 256;
            int row = idx >> 3;
            int cf  = (idx & 7) << 2;
            uint32_t soff = (uint32_t)row * ROWB + (uint32_t)cf * 2;

            float4 va;
            if (GATHER_A) {
                int m = bm + row;
                int b = m >> 11, s = m & 2047;
                int h = it >> 1, dl = ((it & 1) << 5) + cf;
                va = *(const float4*)(A + ((((b << 4) + h) * SEQ + s) << 6) + dl);
            } else {
                va = *(const float4*)(A + (size_t)(bm + row) * DM + k0 + cf);
            }
            *(uint2*)(smem + OFF_AHI + soff) =
                make_uint2(pack_bf16(va.x, va.y), pack_bf16(va.z, va.w));
            *(uint2*)(smem + OFF_ALO + soff) =
                make_uint2(pack_bf16(va.x - rb(va.x), va.y - rb(va.y)),
                           pack_bf16(va.z - rb(va.z), va.w - rb(va.w)));

            float4 vw = *(const float4*)(W + (size_t)(bn + row) * DM + k0 + cf);
            *(uint2*)(smem + OFF_BHI + soff) =
                make_uint2(pack_bf16(vw.x, vw.y), pack_bf16(vw.z, vw.w));
            *(uint2*)(smem + OFF_BLO + soff) =
                make_uint2(pack_bf16(vw.x - rb(vw.x), vw.y - rb(vw.y)),
                           pack_bf16(vw.z - rb(vw.z), vw.w - rb(vw.w)));
        }
        __syncthreads();

#pragma unroll
        for (int ks = 0; ks < 2; ks++) {
            const uint32_t offk = (uint32_t)ks * 32;
            uint32_t ah[4][4], al[4][4], bh[2][4], bl[2][4];
#pragma unroll
            for (int fm = 0; fm < 4; fm++) {
                LDSM4(ah[fm], a_base + fm * (16 * ROWB) + offk);
                LDSM4(al[fm], a_base + (OFF_ALO - OFF_AHI) + fm * (16 * ROWB) + offk);
            }
#pragma unroll
            for (int p = 0; p < 2; p++) {
                LDSM4(bh[p], b_base + p * (16 * ROWB) + offk);
                LDSM4(bl[p], b_base + (OFF_BLO - OFF_BHI) + p * (16 * ROWB) + offk);
            }
#pragma unroll
            for (int fm = 0; fm < 4; fm++)
#pragma unroll
                for (int fn = 0; fn < 4; fn++) {
                    const int p = fn >> 1, o = (fn & 1) << 1;
                    MMA16816(acc[fm][fn], ah[fm], bh[p][o], bh[p][o + 1]);
                    MMA16816(acc[fm][fn], ah[fm], bl[p][o], bl[p][o + 1]);
                    MMA16816(acc[fm][fn], al[fm], bh[p][o], bh[p][o + 1]);
                }
        }
    }

    const int qrow = lid >> 2;
    const int qcol = (lid & 3) << 1;
#pragma unroll
    for (int fm = 0; fm < 4; fm++) {
        int m1 = bm + warp_m * 64 + fm * 16 + qrow;
        int m2 = m1 + 8;
#pragma unroll
        for (int fn = 0; fn < 4; fn++) {
            int n = bn + warp_n * 32 + fn * 8 + qcol;
            float2 bb = *(const float2*)(bias + n);
            float2 v1 = make_float2(acc[fm][fn][0] + bb.x, acc[fm][fn][1] + bb.y);
            float2 v2 = make_float2(acc[fm][fn][2] + bb.x, acc[fm][fn][3] + bb.y);
            if (SPLIT_OUT) {
                int h = n >> 6, dl = n & 63;
                int b1 = m1 >> 11, s1 = m1 & 2047;
                int b2 = m2 >> 11, s2 = m2 & 2047;
                *(float2*)(C + ((((b1 << 4) + h) * SEQ + s1) << 6) + dl) = v1;
                *(float2*)(C + ((((b2 << 4) + h) * SEQ + s2) << 6) + dl) = v2;
            } else {
                *(float2*)(C + (size_t)m1 * DM + n) = v1;
                *(float2*)(C + (size_t)m2 * DM + n) = v2;
            }
        }
    }
}

// ===========================================================================
// Tensor-core flash attention, split-bf16 (scores AND P@V 3-term split).
// CTA: 128 q-rows of one (b,h). 8 warps x m16. K-tile = 64 keys.
// Smem rows: 144B stride (ldmatrix conflict-free: 4r mod 32 distinct).
// V transposed through fp32 staging (row stride 65 floats: conflict-free).
// ===========================================================================
#define AROWB 144
#define AKHI  0
#define AKLO  (64 * AROWB)        //  9216
#define AVTHI (2 * 64 * AROWB)    // 18432
#define AVTLO (3 * 64 * AROWB)    // 27648
#define AVST  (4 * 64 * AROWB)    // 36864 (fp32 staging, stride 65)
#define AQHI  0                   // Q staging overlaps K/VT region (pre-loop)
#define AQLO  (128 * AROWB)       // 18432
#define ATT_SMEM (AVST + 64 * 65 * 4)   // 53504

__global__ __launch_bounds__(256)
void attn_mma(const float* __restrict__ Q, const float* __restrict__ K,
              const float* __restrict__ V, float* __restrict__ O)
{
    extern __shared__ char smem[];
    const uint32_t sb = smem_u32(smem);
    const int tid = threadIdx.x, wid = tid >> 5, lid = tid & 31;
    const int grp = lid >> 3, r = lid & 7;

    const int bh = blockIdx.z * NH + blockIdx.y;
    const int q0 = blockIdx.x * 128;
    const float* Qp = Q + (size_t)(bh * SEQ + q0) * DEPTH;
    const float* Kp = K + (size_t)bh * SEQ * DEPTH;
    const float* Vp = V + (size_t)bh * SEQ * DEPTH;
    float*       Op = O + (size_t)(bh * SEQ + q0) * DEPTH;

    // ---- stage Q (scaled by 0.125, exact), split hi/lo ----
#pragma unroll
    for (int l = 0; l < 8; l++) {
        int idx = tid + l * 256;          // 0..2047
        int row = idx >> 4, c4 = (idx & 15) << 2;
        float4 v = *(const float4*)(Qp + row * DEPTH + c4);
        v.x *= 0.125f; v.y *= 0.125f; v.z *= 0.125f; v.w *= 0.125f;
        uint32_t soff = (uint32_t)row * AROWB + (uint32_t)c4 * 2;
        *(uint2*)(smem + AQHI + soff) =
            make_uint2(pack_bf16(v.x, v.y), pack_bf16(v.z, v.w));
        *(uint2*)(smem + AQLO + soff) =
            make_uint2(pack_bf16(v.x - rb(v.x), v.y - rb(v.y)),
                       pack_bf16(v.z - rb(v.z), v.w - rb(v.w)));
    }
    __syncthreads();

    // ---- Q fragments (A operand, m16k16 x 4 ksteps), hi+lo, kept in regs ----
    uint32_t qh[4][4], ql[4][4];
    {
        uint32_t qbase = sb + (uint32_t)(wid * 16 + ((grp & 1) << 3) + r) * AROWB
                       + (uint32_t)(((grp >> 1) & 1) << 4);
#pragma unroll
        for (int ks = 0; ks < 4; ks++) {
            LDSM4(qh[ks], qbase + AQHI + ks * 32);
            LDSM4(ql[ks], qbase + AQLO + ks * 32);
        }
    }

    // B-operand ldmatrix base (validated pattern: [n][k] k-contiguous rows)
    const uint32_t bbase = sb + (uint32_t)(((grp & 2) << 2) + r) * AROWB
                         + (uint32_t)((grp & 1) << 4);

    float o[8][4];
#pragma unroll
    for (int fn = 0; fn < 8; fn++)
#pragma unroll
        for (int e = 0; e < 4; e++) o[fn][e] = 0.f;
    float m1 = -1e30f, m2 = -1e30f, l1 = 0.f, l2 = 0.f;

    const int vd = tid & 63, vkg = tid >> 6;   // transpose role
    float* vstage = (float*)(smem + AVST);

    for (int kt = 0; kt < SEQ / 64; kt++) {
        __syncthreads();   // (a) prior-iter MMA reads / epilogue done

        // ---- load K (split hi/lo) and V (fp32 staging) ----
        const float* Kt = Kp + kt * 64 * DEPTH;
        const float* Vt = Vp + kt * 64 * DEPTH;
#pragma unroll
        for (int l = 0; l < 4; l++) {
            int idx = tid + l * 256;       // 0..1023
            int row = idx >> 4, c4 = (idx & 15) << 2;
            uint32_t soff = (uint32_t)row * AROWB + (uint32_t)c4 * 2;
            float4 kv = *(const float4*)(Kt + row * DEPTH + c4);
            *(uint2*)(smem + AKHI + soff) =
                make_uint2(pack_bf16(kv.x, kv.y), pack_bf16(kv.z, kv.w));
            *(uint2*)(smem + AKLO + soff) =
                make_uint2(pack_bf16(kv.x - rb(kv.x), kv.y - rb(kv.y)),
                           pack_bf16(kv.z - rb(kv.z), kv.w - rb(kv.w)));
            float4 vv = *(const float4*)(Vt + row * DEPTH + c4);
            vstage[row * 65 + c4 + 0] = vv.x;
            vstage[row * 65 + c4 + 1] = vv.y;
            vstage[row * 65 + c4 + 2] = vv.z;
            vstage[row * 65 + c4 + 3] = vv.w;
        }
        __syncthreads();   // (b)

        // ---- scores: s(16x64) = Qhi*Khi + Qhi*Klo + Qlo*Khi ----
        float s[8][4];
#pragma unroll
        for (int fn = 0; fn < 8; fn++)
#pragma unroll
            for (int e = 0; e < 4; e++) s[fn][e] = 0.f;

#pragma unroll
        for (int ks = 0; ks < 4; ks++) {
            uint32_t kh[4][4], kl[4][4];
#pragma unroll
            for (int p = 0; p < 4; p++) {
                LDSM4(kh[p], bbase + AKHI + p * (16 * AROWB) + ks * 32);
                LDSM4(kl[p], bbase + AKLO + p * (16 * AROWB) + ks * 32);
            }
#pragma unroll
            for (int fn = 0; fn < 8; fn++) {
                const int p = fn >> 1, o2 = (fn & 1) << 1;
                MMA16816(s[fn], qh[ks], kh[p][o2], kh[p][o2 + 1]);
                MMA16816(s[fn], qh[ks], kl[p][o2], kl[p][o2 + 1]);
                MMA16816(s[fn], ql[ks], kh[p][o2], kh[p][o2 + 1]);
            }
        }

        // ---- online softmax; rows r1=lid>>2, r2=r1+8; quad reduction ----
        float mx1 = -1e30f, mx2 = -1e30f;
#pragma unroll
        for (int fn = 0; fn < 8; fn++) {
            mx1 = fmaxf(mx1, fmaxf(s[fn][0], s[fn][1]));
            mx2 = fmaxf(mx2, fmaxf(s[fn][2], s[fn][3]));
        }
        mx1 = fmaxf(mx1, __shfl_xor_sync(0xffffffffu, mx1, 1));
        mx1 = fmaxf(mx1, __shfl_xor_sync(0xffffffffu, mx1, 2));
        mx2 = fmaxf(mx2, __shfl_xor_sync(0xffffffffu, mx2, 1));
        mx2 = fmaxf(mx2, __shfl_xor_sync(0xffffffffu, mx2, 2));

        float mn1 = fmaxf(m1, mx1), mn2 = fmaxf(m2, mx2);
        float c1 = __expf(m1 - mn1), c2 = __expf(m2 - mn2);
        m1 = mn1; m2 = mn2;

        float rs1 = 0.f, rs2 = 0.f;
#pragma unroll
        for (int fn = 0; fn < 8; fn++) {
            s[fn][0] = __expf(s[fn][0] - m1);
            s[fn][1] = __expf(s[fn][1] - m1);
            s[fn][2] = __expf(s[fn][2] - m2);
            s[fn][3] = __expf(s[fn][3] - m2);
            rs1 += s[fn][0] + s[fn][1];
            rs2 += s[fn][2] + s[fn][3];
        }
        rs1 += __shfl_xor_sync(0xffffffffu, rs1, 1);
        rs1 += __shfl_xor_sync(0xffffffffu, rs1, 2);
        rs2 += __shfl_xor_sync(0xffffffffu, rs2, 1);
        rs2 += __shfl_xor_sync(0xffffffffu, rs2, 2);
        l1 = l1 * c1 + rs1;
        l2 = l2 * c2 + rs2;
#pragma unroll
        for (int fn = 0; fn < 8; fn++) {
            o[fn][0] *= c1; o[fn][1] *= c1;
            o[fn][2] *= c2; o[fn][3] *= c2;
        }

        // ---- transpose V: staging -> VT[depth][keys] bf16 hi/lo ----
#pragma unroll
        for (int i = 0; i < 8; i++) {
            int key = vkg * 16 + i * 2;
            float v0 = vstage[key * 65 + vd];
            float v1 = vstage[(key + 1) * 65 + vd];
            *(uint32_t*)(smem + AVTHI + vd * AROWB + key * 2) = pack_bf16(v0, v1);
            *(uint32_t*)(smem + AVTLO + vd * AROWB + key * 2) =
                pack_bf16(v0 - rb(v0), v1 - rb(v1));
        }
        __syncthreads();   // (c) VT ready

        // ---- O += P @ V : Phi*Vhi + Phi*Vlo + Plo*Vhi ----
#pragma unroll
        for (int ks = 0; ks < 4; ks++) {
            // P A-fragments: register permutation of score frags 2ks, 2ks+1
            uint32_t pah[4], pal[4];
            {
                float p0 = s[2 * ks][0],     p1 = s[2 * ks][1];
                float p2 = s[2 * ks][2],     p3 = s[2 * ks][3];
                float p4 = s[2 * ks + 1][0], p5 = s[2 * ks + 1][1];
                float p6 = s[2 * ks + 1][2], p7 = s[2 * ks + 1][3];
                pah[0] = pack_bf16(p0, p1);  pah[1] = pack_bf16(p2, p3);
                pah[2] = pack_bf16(p4, p5);  pah[3] = pack_bf16(p6, p7);
                pal[0] = pack_bf16(p0 - rb(p0), p1 - rb(p1));
                pal[1] = pack_bf16(p2 - rb(p2), p3 - rb(p3));
                pal[2] = pack_bf16(p4 - rb(p4), p5 - rb(p5));
                pal[3] = pack_bf16(p6 - rb(p6), p7 - rb(p7));
            }
            uint32_t vh[4][4], vl[4][4];
#pragma unroll
            for (int p = 0; p < 4; p++) {
                LDSM4(vh[p], bbase + AVTHI + p * (16 * AROWB) + ks * 32);
                LDSM4(vl[p], bbase + AVTLO + p * (16 * AROWB) + ks * 32);
            }
#pragma unroll
            for (int fn = 0; fn < 8; fn++) {
                const int p = fn >> 1, o2 = (fn & 1) << 1;
                MMA16816(o[fn], pah, vh[p][o2], vh[p][o2 + 1]);
                MMA16816(o[fn], pah, vl[p][o2], vl[p][o2 + 1]);
                MMA16816(o[fn], pal, vh[p][o2], vh[p][o2 + 1]);
            }
        }
    }

    // ---- epilogue: normalize, store [row][depth] ----
    float inv1 = 1.f / l1, inv2 = 1.f / l2;
    int qr1 = wid * 16 + (lid >> 2);
    int qr2 = qr1 + 8;
#pragma unroll
    for (int fn = 0; fn < 8; fn++) {
        int col = fn * 8 + (lid & 3) * 2;
        *(float2*)(Op + qr1 * DEPTH + col) =
            make_float2(o[fn][0] * inv1, o[fn][1] * inv1);
        *(float2*)(Op + qr2 * DEPTH + col) =
            make_float2(o[fn][2] * inv2, o[fn][3] * inv2);
    }
}

// ---------------------------------------------------------------------------
extern "C" void kernel_launch(void* const* d_in, const int* in_sizes, int n_in,
                              void* d_out, int out_size)
{
    const float* q  = (const float*)d_in[0];
    const float* k  = (const float*)d_in[1];
    const float* v  = (const float*)d_in[2];
    const float* wq = (const float*)d_in[3];
    const float* bq = (const float*)d_in[4];
    const float* wk = (const float*)d_in[5];
    const float* bk = (const float*)d_in[6];
    const float* wv = (const float*)d_in[7];
    const float* bv = (const float*)d_in[8];
    const float* wo = (const float*)d_in[9];
    const float* bo = (const float*)d_in[10];
    float* out = (float*)d_out;

    float *gQ, *gK, *gV, *gO;
    cudaGetSymbolAddress((void**)&gQ, g_Q);
    cudaGetSymbolAddress((void**)&gK, g_K);
    cudaGetSymbolAddress((void**)&gV, g_V);
    cudaGetSymbolAddress((void**)&gO, g_O);

    dim3 gproj(MTOT / 128, DM / 128);  // (32, 8)

    gemm_mma<false, true><<<gproj, 256, GEMM_SMEM>>>(q, wq, bq, gQ);
    gemm_mma<false, true><<<gproj, 256, GEMM_SMEM>>>(k, wk, bk, gK);
    gemm_mma<false, true><<<gproj, 256, GEMM_SMEM>>>(v, wv, bv, gV);

    cudaFuncSetAttribute(attn_mma, cudaFuncAttributeMaxDynamicSharedMemorySize,
                         ATT_SMEM);
    attn_mma<<<dim3(SEQ / 128, NH, BATCH), 256, ATT_SMEM>>>(gQ, gK, gV, gO);

    gemm_mma<true, false><<<gproj, 256, GEMM_SMEM>>>(gO, wo, bo, out);
}

// round 5
// speedup vs baseline: 3.2128x; 1.0197x over previous
#include <cuda_runtime.h>
#include <cuda_bf16.h>
#include <cstdint>
#include <math.h>

#define BATCH 2
#define SEQ   2048
#define DM    1024
#define NH    16
#define DEPTH 64
#define MTOT  (BATCH*SEQ)   // 4096

// Scratch: head-split activations [B, H, S, depth] (16 MB each)
__device__ float g_Q[BATCH*NH*SEQ*DEPTH];
__device__ float g_K[BATCH*NH*SEQ*DEPTH];
__device__ float g_V[BATCH*NH*SEQ*DEPTH];
__device__ float g_O[BATCH*NH*SEQ*DEPTH];

// ===========================================================================
// helpers
// ===========================================================================
__device__ __forceinline__ uint32_t smem_u32(const void* p) {
    uint32_t a;
    asm("{ .reg .u64 t; cvta.to.shared.u64 t, %1; cvt.u32.u64 %0, t; }"
        : "=r"(a) : "l"(p));
    return a;
}
__device__ __forceinline__ uint32_t pack_bf16(float x, float y) {
    uint32_t lo = __bfloat16_as_ushort(__float2bfloat16(x));
    uint32_t hi = __bfloat16_as_ushort(__float2bfloat16(y));
    return lo | (hi << 16);
}
__device__ __forceinline__ float rb(float x) {   // round to bf16, back to f32
    return __bfloat162float(__float2bfloat16(x));
}

#define LDSM4(R, addr) \
    asm volatile("ldmatrix.sync.aligned.m8n8.x4.shared.b16 {%0,%1,%2,%3}, [%4];" \
        : "=r"((R)[0]), "=r"((R)[1]), "=r"((R)[2]), "=r"((R)[3]) : "r"(addr))

#define MMA16816(D, A, B0, B1) \
    asm volatile("mma.sync.aligned.m16n8k16.row.col.f32.bf16.bf16.f32 " \
        "{%0,%1,%2,%3}, {%4,%5,%6,%7}, {%8,%9}, {%0,%1,%2,%3};" \
        : "+f"((D)[0]), "+f"((D)[1]), "+f"((D)[2]), "+f"((D)[3]) \
        : "r"((A)[0]), "r"((A)[1]), "r"((A)[2]), "r"((A)[3]), "r"(B0), "r"(B1))

#define CP16(dst, src) \
    asm volatile("cp.async.cg.shared.global [%0], [%1], 16;" \
        :: "r"(dst), "l"(src) : "memory")
#define CP_COMMIT()  asm volatile("cp.async.commit_group;" ::: "memory")
#define CP_WAIT1()   asm volatile("cp.async.wait_group 1;" ::: "memory")

// ===========================================================================
// Split-bf16 tensor-core GEMM + cp.async double-buffered staging.
//   C[m,n] = sum_k A[m,k]*W[n,k] + bias[n]
// CTA 128x128, BK=32, 8 warps (2m x 4n). bf16 smem rows: 80B stride.
// fp32 staging: 128 rows x 128B per matrix per buffer.
// ===========================================================================
#define ROWB 80
#define MAT_BYTES (128 * ROWB)          // 10240
#define OFF_AHI 0
#define OFF_ALO (MAT_BYTES)
#define OFF_BHI (2 * MAT_BYTES)
#define OFF_BLO (3 * MAT_BYTES)
#define GSTG_A  (4 * MAT_BYTES)         // 40960
#define GSTG_W  (GSTG_A + 2 * 16384)    // 73728
#define GEMM_SMEM (GSTG_W + 2 * 16384)  // 106496

template<bool GATHER_A, bool SPLIT_OUT>
__global__ __launch_bounds__(256)
void gemm_mma(const float* __restrict__ A, const float* __restrict__ W,
              const float* __restrict__ bias, float* __restrict__ C)
{
    extern __shared__ char smem[];
    const uint32_t sb = smem_u32(smem);

    const int tid = threadIdx.x;
    const int wid = tid >> 5, lid = tid & 31;
    const int warp_m = wid >> 2;
    const int warp_n = wid & 3;
    const int bm = blockIdx.x * 128, bn = blockIdx.y * 128;

    const int grp = lid >> 3, r = lid & 7;
    const uint32_t a_base = sb + OFF_AHI
        + (uint32_t)(warp_m * 64 + ((grp & 1) << 3) + r) * ROWB
        + (uint32_t)(((grp >> 1) & 1) << 4);
    const uint32_t b_base = sb + OFF_BHI
        + (uint32_t)(warp_n * 32 + (((grp >> 1) & 1) << 3) + r) * ROWB
        + (uint32_t)((grp & 1) << 4);

    // cp.async issue helper coords: idx = tid + l*256 -> row=idx>>3, c4=(idx&7)*4
    auto issue_tile = [&](int it) {
        const int k0 = it * 32;
        const uint32_t buf = (uint32_t)(it & 1) * 16384u;
#pragma unroll
        for (int l = 0; l < 4; l++) {
            int idx = tid + l * 256;
            int row = idx >> 3;
            int cf  = (idx & 7) << 2;
            uint32_t doff = (uint32_t)row * 128 + (uint32_t)cf * 4;
            const float* srcA;
            if (GATHER_A) {
                int m = bm + row;
                int b = m >> 11, s = m & 2047;
                int h = it >> 1, dl = ((it & 1) << 5) + cf;
                srcA = A + ((((b << 4) + h) * SEQ + s) << 6) + dl;
            } else {
                srcA = A + (size_t)(bm + row) * DM + k0 + cf;
            }
            CP16(sb + GSTG_A + buf + doff, srcA);
            CP16(sb + GSTG_W + buf + doff,
                 W + (size_t)(bn + row) * DM + k0 + cf);
        }
    };

    float acc[4][4][4];
#pragma unroll
    for (int i = 0; i < 4; i++)
#pragma unroll
        for (int j = 0; j < 4; j++)
#pragma unroll
            for (int e = 0; e < 4; e++) acc[i][j][e] = 0.f;

    issue_tile(0);
    CP_COMMIT();

    for (int it = 0; it < DM / 32; it++) {
        if (it + 1 < DM / 32) issue_tile(it + 1);
        CP_COMMIT();
        CP_WAIT1();
        __syncthreads();   // staging buf[it&1] ready for all; bf16 regions free

        // ---- convert fp32 staging -> bf16 hi/lo smem ----
        const float* stA = (const float*)(smem + GSTG_A + (it & 1) * 16384);
        const float* stW = (const float*)(smem + GSTG_W + (it & 1) * 16384);
#pragma unroll
        for (int l = 0; l < 4; l++) {
            int idx = tid + l * 256;
            int row = idx >> 3;
            int cf  = (idx & 7) << 2;
            uint32_t soff = (uint32_t)row * ROWB + (uint32_t)cf * 2;
            float4 va = *(const float4*)(stA + row * 32 + cf);
            *(uint2*)(smem + OFF_AHI + soff) =
                make_uint2(pack_bf16(va.x, va.y), pack_bf16(va.z, va.w));
            *(uint2*)(smem + OFF_ALO + soff) =
                make_uint2(pack_bf16(va.x - rb(va.x), va.y - rb(va.y)),
                           pack_bf16(va.z - rb(va.z), va.w - rb(va.w)));
            float4 vw = *(const float4*)(stW + row * 32 + cf);
            *(uint2*)(smem + OFF_BHI + soff) =
                make_uint2(pack_bf16(vw.x, vw.y), pack_bf16(vw.z, vw.w));
            *(uint2*)(smem + OFF_BLO + soff) =
                make_uint2(pack_bf16(vw.x - rb(vw.x), vw.y - rb(vw.y)),
                           pack_bf16(vw.z - rb(vw.z), vw.w - rb(vw.w)));
        }
        __syncthreads();

#pragma unroll
        for (int ks = 0; ks < 2; ks++) {
            const uint32_t offk = (uint32_t)ks * 32;
            uint32_t ah[4][4], al[4][4], bh[2][4], bl[2][4];
#pragma unroll
            for (int fm = 0; fm < 4; fm++) {
                LDSM4(ah[fm], a_base + fm * (16 * ROWB) + offk);
                LDSM4(al[fm], a_base + (OFF_ALO - OFF_AHI) + fm * (16 * ROWB) + offk);
            }
#pragma unroll
            for (int p = 0; p < 2; p++) {
                LDSM4(bh[p], b_base + p * (16 * ROWB) + offk);
                LDSM4(bl[p], b_base + (OFF_BLO - OFF_BHI) + p * (16 * ROWB) + offk);
            }
#pragma unroll
            for (int fm = 0; fm < 4; fm++)
#pragma unroll
                for (int fn = 0; fn < 4; fn++) {
                    const int p = fn >> 1, o = (fn & 1) << 1;
                    MMA16816(acc[fm][fn], ah[fm], bh[p][o], bh[p][o + 1]);
                    MMA16816(acc[fm][fn], ah[fm], bl[p][o], bl[p][o + 1]);
                    MMA16816(acc[fm][fn], al[fm], bh[p][o], bh[p][o + 1]);
                }
        }
    }

    const int qrow = lid >> 2;
    const int qcol = (lid & 3) << 1;
#pragma unroll
    for (int fm = 0; fm < 4; fm++) {
        int m1 = bm + warp_m * 64 + fm * 16 + qrow;
        int m2 = m1 + 8;
#pragma unroll
        for (int fn = 0; fn < 4; fn++) {
            int n = bn + warp_n * 32 + fn * 8 + qcol;
            float2 bb = *(const float2*)(bias + n);
            float2 v1 = make_float2(acc[fm][fn][0] + bb.x, acc[fm][fn][1] + bb.y);
            float2 v2 = make_float2(acc[fm][fn][2] + bb.x, acc[fm][fn][3] + bb.y);
            if (SPLIT_OUT) {
                int h = n >> 6, dl = n & 63;
                int b1 = m1 >> 11, s1 = m1 & 2047;
                int b2 = m2 >> 11, s2 = m2 & 2047;
                *(float2*)(C + ((((b1 << 4) + h) * SEQ + s1) << 6) + dl) = v1;
                *(float2*)(C + ((((b2 << 4) + h) * SEQ + s2) << 6) + dl) = v2;
            } else {
                *(float2*)(C + (size_t)m1 * DM + n) = v1;
                *(float2*)(C + (size_t)m2 * DM + n) = v2;
            }
        }
    }
}

// ===========================================================================
// Tensor-core flash attention, split-bf16, cp.async double-buffered K/V.
// CTA: 128 q-rows; 8 warps x m16; 64-key tiles; 2 barriers/iter.
// bf16 rows 144B stride; fp32 staging rows 272B (68 floats) stride.
// ===========================================================================
#define AROWB 144
#define AKHI  0
#define AKLO  (64 * AROWB)        //  9216
#define AVTHI (2 * 64 * AROWB)    // 18432
#define AVTLO (3 * 64 * AROWB)    // 27648
#define ASTK  (4 * 64 * AROWB)    // 36864  stageK: 2 x 17408
#define ASTV  (ASTK + 2 * 17408)  // 71680  stageV: 2 x 17408
#define AQHI  0                   // Q staging overlaps K/VT region (pre-loop)
#define AQLO  (128 * AROWB)       // 18432
#define ATT_SMEM (ASTV + 2 * 17408)   // 106496

__global__ __launch_bounds__(256)
void attn_mma(const float* __restrict__ Q, const float* __restrict__ K,
              const float* __restrict__ V, float* __restrict__ O)
{
    extern __shared__ char smem[];
    const uint32_t sb = smem_u32(smem);
    const int tid = threadIdx.x, wid = tid >> 5, lid = tid & 31;
    const int grp = lid >> 3, r = lid & 7;

    const int bh = blockIdx.z * NH + blockIdx.y;
    const int q0 = blockIdx.x * 128;
    const float* Qp = Q + (size_t)(bh * SEQ + q0) * DEPTH;
    const float* Kp = K + (size_t)bh * SEQ * DEPTH;
    const float* Vp = V + (size_t)bh * SEQ * DEPTH;
    float*       Op = O + (size_t)(bh * SEQ + q0) * DEPTH;

    auto issue_tile = [&](int kt) {
        const uint32_t buf = (uint32_t)(kt & 1) * 17408u;
        const float* Kt = Kp + kt * 64 * DEPTH;
        const float* Vt = Vp + kt * 64 * DEPTH;
#pragma unroll
        for (int l = 0; l < 4; l++) {
            int idx = tid + l * 256;       // 0..1023
            int row = idx >> 4, c4 = (idx & 15) << 2;
            uint32_t doff = (uint32_t)row * 272 + (uint32_t)c4 * 4;
            CP16(sb + ASTK + buf + doff, Kt + row * DEPTH + c4);
            CP16(sb + ASTV + buf + doff, Vt + row * DEPTH + c4);
        }
    };

    // prologue: start tile 0 before doing Q work
    issue_tile(0);
    CP_COMMIT();

    // ---- stage Q (scaled by 0.125, exact), split hi/lo ----
#pragma unroll
    for (int l = 0; l < 8; l++) {
        int idx = tid + l * 256;
        int row = idx >> 4, c4 = (idx & 15) << 2;
        float4 v = *(const float4*)(Qp + row * DEPTH + c4);
        v.x *= 0.125f; v.y *= 0.125f; v.z *= 0.125f; v.w *= 0.125f;
        uint32_t soff = (uint32_t)row * AROWB + (uint32_t)c4 * 2;
        *(uint2*)(smem + AQHI + soff) =
            make_uint2(pack_bf16(v.x, v.y), pack_bf16(v.z, v.w));
        *(uint2*)(smem + AQLO + soff) =
            make_uint2(pack_bf16(v.x - rb(v.x), v.y - rb(v.y)),
                       pack_bf16(v.z - rb(v.z), v.w - rb(v.w)));
    }
    __syncthreads();

    // ---- Q fragments (A operand, 4 ksteps), hi+lo, in registers ----
    uint32_t qh[4][4], ql[4][4];
    {
        uint32_t qbase = sb + (uint32_t)(wid * 16 + ((grp & 1) << 3) + r) * AROWB
                       + (uint32_t)(((grp >> 1) & 1) << 4);
#pragma unroll
        for (int ks = 0; ks < 4; ks++) {
            LDSM4(qh[ks], qbase + AQHI + ks * 32);
            LDSM4(ql[ks], qbase + AQLO + ks * 32);
        }
    }

    const uint32_t bbase = sb + (uint32_t)(((grp & 2) << 2) + r) * AROWB
                         + (uint32_t)((grp & 1) << 4);

    float o[8][4];
#pragma unroll
    for (int fn = 0; fn < 8; fn++)
#pragma unroll
        for (int e = 0; e < 4; e++) o[fn][e] = 0.f;
    float m1 = -1e30f, m2 = -1e30f, l1 = 0.f, l2 = 0.f;

    const int vd = tid & 63, vkg = tid >> 6;   // transpose role

    for (int kt = 0; kt < SEQ / 64; kt++) {
        if (kt + 1 < SEQ / 64) issue_tile(kt + 1);
        CP_COMMIT();
        CP_WAIT1();
        __syncthreads();   // staging[kt&1] ready; bf16 regions free (Q frags done)

        const float* stK = (const float*)(smem + ASTK + (kt & 1) * 17408);
        const float* stV = (const float*)(smem + ASTV + (kt & 1) * 17408);

        // ---- convert K: fp32 staging -> bf16 hi/lo ----
#pragma unroll
        for (int l = 0; l < 4; l++) {
            int idx = tid + l * 256;
            int row = idx >> 4, c4 = (idx & 15) << 2;
            uint32_t soff = (uint32_t)row * AROWB + (uint32_t)c4 * 2;
            float4 kv = *(const float4*)(stK + row * 68 + c4);
            *(uint2*)(smem + AKHI + soff) =
                make_uint2(pack_bf16(kv.x, kv.y), pack_bf16(kv.z, kv.w));
            *(uint2*)(smem + AKLO + soff) =
                make_uint2(pack_bf16(kv.x - rb(kv.x), kv.y - rb(kv.y)),
                           pack_bf16(kv.z - rb(kv.z), kv.w - rb(kv.w)));
        }
        // ---- transpose V: staging -> VT[depth][keys] bf16 hi/lo ----
#pragma unroll
        for (int i = 0; i < 8; i++) {
            int key = vkg * 16 + i * 2;
            float v0 = stV[key * 68 + vd];
            float v1 = stV[(key + 1) * 68 + vd];
            *(uint32_t*)(smem + AVTHI + vd * AROWB + key * 2) = pack_bf16(v0, v1);
            *(uint32_t*)(smem + AVTLO + vd * AROWB + key * 2) =
                pack_bf16(v0 - rb(v0), v1 - rb(v1));
        }
        __syncthreads();   // bf16 K / VT ready

        // ---- scores: s(16x64) = Qhi*Khi + Qhi*Klo + Qlo*Khi ----
        float s[8][4];
#pragma unroll
        for (int fn = 0; fn < 8; fn++)
#pragma unroll
            for (int e = 0; e < 4; e++) s[fn][e] = 0.f;

#pragma unroll
        for (int ks = 0; ks < 4; ks++) {
            uint32_t kh[4][4], kl[4][4];
#pragma unroll
            for (int p = 0; p < 4; p++) {
                LDSM4(kh[p], bbase + AKHI + p * (16 * AROWB) + ks * 32);
                LDSM4(kl[p], bbase + AKLO + p * (16 * AROWB) + ks * 32);
            }
#pragma unroll
            for (int fn = 0; fn < 8; fn++) {
                const int p = fn >> 1, o2 = (fn & 1) << 1;
                MMA16816(s[fn], qh[ks], kh[p][o2], kh[p][o2 + 1]);
                MMA16816(s[fn], qh[ks], kl[p][o2], kl[p][o2 + 1]);
                MMA16816(s[fn], ql[ks], kh[p][o2], kh[p][o2 + 1]);
            }
        }

        // ---- online softmax (rows r1=lid>>2, r2=r1+8; quad reduction) ----
        float mx1 = -1e30f, mx2 = -1e30f;
#pragma unroll
        for (int fn = 0; fn < 8; fn++) {
            mx1 = fmaxf(mx1, fmaxf(s[fn][0], s[fn][1]));
            mx2 = fmaxf(mx2, fmaxf(s[fn][2], s[fn][3]));
        }
        mx1 = fmaxf(mx1, __shfl_xor_sync(0xffffffffu, mx1, 1));
        mx1 = fmaxf(mx1, __shfl_xor_sync(0xffffffffu, mx1, 2));
        mx2 = fmaxf(mx2, __shfl_xor_sync(0xffffffffu, mx2, 1));
        mx2 = fmaxf(mx2, __shfl_xor_sync(0xffffffffu, mx2, 2));

        float mn1 = fmaxf(m1, mx1), mn2 = fmaxf(m2, mx2);
        float c1 = __expf(m1 - mn1), c2 = __expf(m2 - mn2);
        m1 = mn1; m2 = mn2;

        float rs1 = 0.f, rs2 = 0.f;
#pragma unroll
        for (int fn = 0; fn < 8; fn++) {
            s[fn][0] = __expf(s[fn][0] - m1);
            s[fn][1] = __expf(s[fn][1] - m1);
            s[fn][2] = __expf(s[fn][2] - m2);
            s[fn][3] = __expf(s[fn][3] - m2);
            rs1 += s[fn][0] + s[fn][1];
            rs2 += s[fn][2] + s[fn][3];
        }
        rs1 += __shfl_xor_sync(0xffffffffu, rs1, 1);
        rs1 += __shfl_xor_sync(0xffffffffu, rs1, 2);
        rs2 += __shfl_xor_sync(0xffffffffu, rs2, 1);
        rs2 += __shfl_xor_sync(0xffffffffu, rs2, 2);
        l1 = l1 * c1 + rs1;
        l2 = l2 * c2 + rs2;
#pragma unroll
        for (int fn = 0; fn < 8; fn++) {
            o[fn][0] *= c1; o[fn][1] *= c1;
            o[fn][2] *= c2; o[fn][3] *= c2;
        }

        // ---- O += P @ V : Phi*Vhi + Phi*Vlo + Plo*Vhi ----
#pragma unroll
        for (int ks = 0; ks < 4; ks++) {
            uint32_t pah[4], pal[4];
            {
                float p0 = s[2 * ks][0],     p1 = s[2 * ks][1];
                float p2 = s[2 * ks][2],     p3 = s[2 * ks][3];
                float p4 = s[2 * ks + 1][0], p5 = s[2 * ks + 1][1];
                float p6 = s[2 * ks + 1][2], p7 = s[2 * ks + 1][3];
                pah[0] = pack_bf16(p0, p1);  pah[1] = pack_bf16(p2, p3);
                pah[2] = pack_bf16(p4, p5);  pah[3] = pack_bf16(p6, p7);
                pal[0] = pack_bf16(p0 - rb(p0), p1 - rb(p1));
                pal[1] = pack_bf16(p2 - rb(p2), p3 - rb(p3));
                pal[2] = pack_bf16(p4 - rb(p4), p5 - rb(p5));
                pal[3] = pack_bf16(p6 - rb(p6), p7 - rb(p7));
            }
            uint32_t vh[4][4], vl[4][4];
#pragma unroll
            for (int p = 0; p < 4; p++) {
                LDSM4(vh[p], bbase + AVTHI + p * (16 * AROWB) + ks * 32);
                LDSM4(vl[p], bbase + AVTLO + p * (16 * AROWB) + ks * 32);
            }
#pragma unroll
            for (int fn = 0; fn < 8; fn++) {
                const int p = fn >> 1, o2 = (fn & 1) << 1;
                MMA16816(o[fn], pah, vh[p][o2], vh[p][o2 + 1]);
                MMA16816(o[fn], pah, vl[p][o2], vl[p][o2 + 1]);
                MMA16816(o[fn], pal, vh[p][o2], vh[p][o2 + 1]);
            }
        }
    }

    // ---- epilogue: normalize, store ----
    float inv1 = 1.f / l1, inv2 = 1.f / l2;
    int qr1 = wid * 16 + (lid >> 2);
    int qr2 = qr1 + 8;
#pragma unroll
    for (int fn = 0; fn < 8; fn++) {
        int col = fn * 8 + (lid & 3) * 2;
        *(float2*)(Op + qr1 * DEPTH + col) =
            make_float2(o[fn][0] * inv1, o[fn][1] * inv1);
        *(float2*)(Op + qr2 * DEPTH + col) =
            make_float2(o[fn][2] * inv2, o[fn][3] * inv2);
    }
}

// ---------------------------------------------------------------------------
extern "C" void kernel_launch(void* const* d_in, const int* in_sizes, int n_in,
                              void* d_out, int out_size)
{
    const float* q  = (const float*)d_in[0];
    const float* k  = (const float*)d_in[1];
    const float* v  = (const float*)d_in[2];
    const float* wq = (const float*)d_in[3];
    const float* bq = (const float*)d_in[4];
    const float* wk = (const float*)d_in[5];
    const float* bk = (const float*)d_in[6];
    const float* wv = (const float*)d_in[7];
    const float* bv = (const float*)d_in[8];
    const float* wo = (const float*)d_in[9];
    const float* bo = (const float*)d_in[10];
    float* out = (float*)d_out;

    float *gQ, *gK, *gV, *gO;
    cudaGetSymbolAddress((void**)&gQ, g_Q);
    cudaGetSymbolAddress((void**)&gK, g_K);
    cudaGetSymbolAddress((void**)&gV, g_V);
    cudaGetSymbolAddress((void**)&gO, g_O);

    cudaFuncSetAttribute(gemm_mma<false, true>,
                         cudaFuncAttributeMaxDynamicSharedMemorySize, GEMM_SMEM);
    cudaFuncSetAttribute(gemm_mma<true, false>,
                         cudaFuncAttributeMaxDynamicSharedMemorySize, GEMM_SMEM);
    cudaFuncSetAttribute(attn_mma,
                         cudaFuncAttributeMaxDynamicSharedMemorySize, ATT_SMEM);

    dim3 gproj(MTOT / 128, DM / 128);  // (32, 8)

    gemm_mma<false, true><<<gproj, 256, GEMM_SMEM>>>(q, wq, bq, gQ);
    gemm_mma<false, true><<<gproj, 256, GEMM_SMEM>>>(k, wk, bk, gK);
    gemm_mma<false, true><<<gproj, 256, GEMM_SMEM>>>(v, wv, bv, gV);

    attn_mma<<<dim3(SEQ / 128, NH, BATCH), 256, ATT_SMEM>>>(gQ, gK, gV, gO);

    gemm_mma<true, false><<<gproj, 256, GEMM_SMEM>>>(gO, wo, bo, out);
}

// round 6
// speedup vs baseline: 3.5902x; 1.1175x over previous
#include <cuda_runtime.h>
#include <cuda_bf16.h>
#include <cstdint>
#include <math.h>

#define BATCH 2
#define SEQ   2048
#define DM    1024
#define NH    16
#define DEPTH 64
#define MTOT  (BATCH*SEQ)   // 4096

// Scratch: head-split activations [B, H, S, depth] (16 MB each)
__device__ float g_Q[BATCH*NH*SEQ*DEPTH];
__device__ float g_K[BATCH*NH*SEQ*DEPTH];
__device__ float g_V[BATCH*NH*SEQ*DEPTH];
__device__ float g_O[BATCH*NH*SEQ*DEPTH];

// ===========================================================================
// helpers
// ===========================================================================
__device__ __forceinline__ uint32_t smem_u32(const void* p) {
    uint32_t a;
    asm("{ .reg .u64 t; cvta.to.shared.u64 t, %1; cvt.u32.u64 %0, t; }"
        : "=r"(a) : "l"(p));
    return a;
}
__device__ __forceinline__ uint32_t pack_bf16(float x, float y) {
    uint32_t lo = __bfloat16_as_ushort(__float2bfloat16(x));
    uint32_t hi = __bfloat16_as_ushort(__float2bfloat16(y));
    return lo | (hi << 16);
}
__device__ __forceinline__ float rb(float x) {   // round to bf16, back to f32
    return __bfloat162float(__float2bfloat16(x));
}

#define LDSM4(R, addr) \
    asm volatile("ldmatrix.sync.aligned.m8n8.x4.shared.b16 {%0,%1,%2,%3}, [%4];" \
        : "=r"((R)[0]), "=r"((R)[1]), "=r"((R)[2]), "=r"((R)[3]) : "r"(addr))

#define MMA16816(D, A, B0, B1) \
    asm volatile("mma.sync.aligned.m16n8k16.row.col.f32.bf16.bf16.f32 " \
        "{%0,%1,%2,%3}, {%4,%5,%6,%7}, {%8,%9}, {%0,%1,%2,%3};" \
        : "+f"((D)[0]), "+f"((D)[1]), "+f"((D)[2]), "+f"((D)[3]) \
        : "r"((A)[0]), "r"((A)[1]), "r"((A)[2]), "r"((A)[3]), "r"(B0), "r"(B1))

#define CP16(dst, src) \
    asm volatile("cp.async.cg.shared.global [%0], [%1], 16;" \
        :: "r"(dst), "l"(src) : "memory")
#define CP_COMMIT()  asm volatile("cp.async.commit_group;" ::: "memory")
#define CP_WAIT1()   asm volatile("cp.async.wait_group 1;" ::: "memory")

// ===========================================================================
// Split-bf16 tensor-core GEMM + cp.async double-buffered staging.
// (unchanged from round 5 — validated)
// ===========================================================================
#define ROWB 80
#define MAT_BYTES (128 * ROWB)
#define OFF_AHI 0
#define OFF_ALO (MAT_BYTES)
#define OFF_BHI (2 * MAT_BYTES)
#define OFF_BLO (3 * MAT_BYTES)
#define GSTG_A  (4 * MAT_BYTES)
#define GSTG_W  (GSTG_A + 2 * 16384)
#define GEMM_SMEM (GSTG_W + 2 * 16384)  // 106496

template<bool GATHER_A, bool SPLIT_OUT>
__global__ __launch_bounds__(256)
void gemm_mma(const float* __restrict__ A, const float* __restrict__ W,
              const float* __restrict__ bias, float* __restrict__ C)
{
    extern __shared__ char smem[];
    const uint32_t sb = smem_u32(smem);

    const int tid = threadIdx.x;
    const int wid = tid >> 5, lid = tid & 31;
    const int warp_m = wid >> 2;
    const int warp_n = wid & 3;
    const int bm = blockIdx.x * 128, bn = blockIdx.y * 128;

    const int grp = lid >> 3, r = lid & 7;
    const uint32_t a_base = sb + OFF_AHI
        + (uint32_t)(warp_m * 64 + ((grp & 1) << 3) + r) * ROWB
        + (uint32_t)(((grp >> 1) & 1) << 4);
    const uint32_t b_base = sb + OFF_BHI
        + (uint32_t)(warp_n * 32 + (((grp >> 1) & 1) << 3) + r) * ROWB
        + (uint32_t)((grp & 1) << 4);

    auto issue_tile = [&](int it) {
        const int k0 = it * 32;
        const uint32_t buf = (uint32_t)(it & 1) * 16384u;
#pragma unroll
        for (int l = 0; l < 4; l++) {
            int idx = tid + l * 256;
            int row = idx >> 3;
            int cf  = (idx & 7) << 2;
            uint32_t doff = (uint32_t)row * 128 + (uint32_t)cf * 4;
            const float* srcA;
            if (GATHER_A) {
                int m = bm + row;
                int b = m >> 11, s = m & 2047;
                int h = it >> 1, dl = ((it & 1) << 5) + cf;
                srcA = A + ((((b << 4) + h) * SEQ + s) << 6) + dl;
            } else {
                srcA = A + (size_t)(bm + row) * DM + k0 + cf;
            }
            CP16(sb + GSTG_A + buf + doff, srcA);
            CP16(sb + GSTG_W + buf + doff,
                 W + (size_t)(bn + row) * DM + k0 + cf);
        }
    };

    float acc[4][4][4];
#pragma unroll
    for (int i = 0; i < 4; i++)
#pragma unroll
        for (int j = 0; j < 4; j++)
#pragma unroll
            for (int e = 0; e < 4; e++) acc[i][j][e] = 0.f;

    issue_tile(0);
    CP_COMMIT();

    for (int it = 0; it < DM / 32; it++) {
        if (it + 1 < DM / 32) issue_tile(it + 1);
        CP_COMMIT();
        CP_WAIT1();
        __syncthreads();

        const float* stA = (const float*)(smem + GSTG_A + (it & 1) * 16384);
        const float* stW = (const float*)(smem + GSTG_W + (it & 1) * 16384);
#pragma unroll
        for (int l = 0; l < 4; l++) {
            int idx = tid + l * 256;
            int row = idx >> 3;
            int cf  = (idx & 7) << 2;
            uint32_t soff = (uint32_t)row * ROWB + (uint32_t)cf * 2;
            float4 va = *(const float4*)(stA + row * 32 + cf);
            *(uint2*)(smem + OFF_AHI + soff) =
                make_uint2(pack_bf16(va.x, va.y), pack_bf16(va.z, va.w));
            *(uint2*)(smem + OFF_ALO + soff) =
                make_uint2(pack_bf16(va.x - rb(va.x), va.y - rb(va.y)),
                           pack_bf16(va.z - rb(va.z), va.w - rb(va.w)));
            float4 vw = *(const float4*)(stW + row * 32 + cf);
            *(uint2*)(smem + OFF_BHI + soff) =
                make_uint2(pack_bf16(vw.x, vw.y), pack_bf16(vw.z, vw.w));
            *(uint2*)(smem + OFF_BLO + soff) =
                make_uint2(pack_bf16(vw.x - rb(vw.x), vw.y - rb(vw.y)),
                           pack_bf16(vw.z - rb(vw.z), vw.w - rb(vw.w)));
        }
        __syncthreads();

#pragma unroll
        for (int ks = 0; ks < 2; ks++) {
            const uint32_t offk = (uint32_t)ks * 32;
            uint32_t ah[4][4], al[4][4], bh[2][4], bl[2][4];
#pragma unroll
            for (int fm = 0; fm < 4; fm++) {
                LDSM4(ah[fm], a_base + fm * (16 * ROWB) + offk);
                LDSM4(al[fm], a_base + (OFF_ALO - OFF_AHI) + fm * (16 * ROWB) + offk);
            }
#pragma unroll
            for (int p = 0; p < 2; p++) {
                LDSM4(bh[p], b_base + p * (16 * ROWB) + offk);
                LDSM4(bl[p], b_base + (OFF_BLO - OFF_BHI) + p * (16 * ROWB) + offk);
            }
#pragma unroll
            for (int fm = 0; fm < 4; fm++)
#pragma unroll
                for (int fn = 0; fn < 4; fn++) {
                    const int p = fn >> 1, o = (fn & 1) << 1;
                    MMA16816(acc[fm][fn], ah[fm], bh[p][o], bh[p][o + 1]);
                    MMA16816(acc[fm][fn], ah[fm], bl[p][o], bl[p][o + 1]);
                    MMA16816(acc[fm][fn], al[fm], bh[p][o], bh[p][o + 1]);
                }
        }
    }

    const int qrow = lid >> 2;
    const int qcol = (lid & 3) << 1;
#pragma unroll
    for (int fm = 0; fm < 4; fm++) {
        int m1 = bm + warp_m * 64 + fm * 16 + qrow;
        int m2 = m1 + 8;
#pragma unroll
        for (int fn = 0; fn < 4; fn++) {
            int n = bn + warp_n * 32 + fn * 8 + qcol;
            float2 bb = *(const float2*)(bias + n);
            float2 v1 = make_float2(acc[fm][fn][0] + bb.x, acc[fm][fn][1] + bb.y);
            float2 v2 = make_float2(acc[fm][fn][2] + bb.x, acc[fm][fn][3] + bb.y);
            if (SPLIT_OUT) {
                int h = n >> 6, dl = n & 63;
                int b1 = m1 >> 11, s1 = m1 & 2047;
                int b2 = m2 >> 11, s2 = m2 & 2047;
                *(float2*)(C + ((((b1 << 4) + h) * SEQ + s1) << 6) + dl) = v1;
                *(float2*)(C + ((((b2 << 4) + h) * SEQ + s2) << 6) + dl) = v2;
            } else {
                *(float2*)(C + (size_t)m1 * DM + n) = v1;
                *(float2*)(C + (size_t)m2 * DM + n) = v2;
            }
        }
    }
}

// ===========================================================================
// Tensor-core flash attention, split-bf16, 2 CTAs/SM.
// Q in a persistent smem region (fragments re-ldmatrix'd per k-step -> fewer
// regs); K/V loaded directly; V transposed via fp32 staging; 3 syncs/iter.
// ===========================================================================
#define AROWB 144
#define AQHI  0                   // Q hi: 128 rows x 144B = 18432
#define AQLO  18432               // Q lo
#define AKHI  36864               // K hi: 64 x 144 = 9216
#define AKLO  46080
#define AVTHI 55296               // VT hi: 64 x 144
#define AVTLO 64512
#define AVST  73728               // V fp32 staging: 64 x 272B = 17408
#define ATT_SMEM (AVST + 17408)   // 91136 -> 2 CTAs/SM (182 KB < 228 KB)

__global__ __launch_bounds__(256, 2)
void attn_mma(const float* __restrict__ Q, const float* __restrict__ K,
              const float* __restrict__ V, float* __restrict__ O)
{
    extern __shared__ char smem[];
    const uint32_t sb = smem_u32(smem);
    const int tid = threadIdx.x, wid = tid >> 5, lid = tid & 31;
    const int grp = lid >> 3, r = lid & 7;

    const int bh = blockIdx.z * NH + blockIdx.y;
    const int q0 = blockIdx.x * 128;
    const float* Qp = Q + (size_t)(bh * SEQ + q0) * DEPTH;
    const float* Kp = K + (size_t)bh * SEQ * DEPTH;
    const float* Vp = V + (size_t)bh * SEQ * DEPTH;
    float*       Op = O + (size_t)(bh * SEQ + q0) * DEPTH;

    // ---- stage Q (scaled by 0.125, exact), split hi/lo; persistent ----
#pragma unroll
    for (int l = 0; l < 8; l++) {
        int idx = tid + l * 256;
        int row = idx >> 4, c4 = (idx & 15) << 2;
        float4 v = *(const float4*)(Qp + row * DEPTH + c4);
        v.x *= 0.125f; v.y *= 0.125f; v.z *= 0.125f; v.w *= 0.125f;
        uint32_t soff = (uint32_t)row * AROWB + (uint32_t)c4 * 2;
        *(uint2*)(smem + AQHI + soff) =
            make_uint2(pack_bf16(v.x, v.y), pack_bf16(v.z, v.w));
        *(uint2*)(smem + AQLO + soff) =
            make_uint2(pack_bf16(v.x - rb(v.x), v.y - rb(v.y)),
                       pack_bf16(v.z - rb(v.z), v.w - rb(v.w)));
    }

    const uint32_t qbase = sb + (uint32_t)(wid * 16 + ((grp & 1) << 3) + r) * AROWB
                         + (uint32_t)(((grp >> 1) & 1) << 4);
    const uint32_t bbase = sb + (uint32_t)(((grp & 2) << 2) + r) * AROWB
                         + (uint32_t)((grp & 1) << 4);

    float o[8][4];
#pragma unroll
    for (int fn = 0; fn < 8; fn++)
#pragma unroll
        for (int e = 0; e < 4; e++) o[fn][e] = 0.f;
    float m1 = -1e30f, m2 = -1e30f, l1 = 0.f, l2 = 0.f;

    const int vd = tid & 63, vkg = tid >> 6;   // transpose role
    float* vstage = (float*)(smem + AVST);

    for (int kt = 0; kt < SEQ / 64; kt++) {
        __syncthreads();   // (a) prev iter readers of K/VT/vstage done (Q ready, kt=0)

        // ---- load K direct -> bf16 hi/lo; V -> fp32 staging ----
        const float* Kt = Kp + kt * 64 * DEPTH;
        const float* Vt = Vp + kt * 64 * DEPTH;
#pragma unroll
        for (int l = 0; l < 4; l++) {
            int idx = tid + l * 256;
            int row = idx >> 4, c4 = (idx & 15) << 2;
            uint32_t soff = (uint32_t)row * AROWB + (uint32_t)c4 * 2;
            float4 kv = *(const float4*)(Kt + row * DEPTH + c4);
            *(uint2*)(smem + AKHI + soff) =
                make_uint2(pack_bf16(kv.x, kv.y), pack_bf16(kv.z, kv.w));
            *(uint2*)(smem + AKLO + soff) =
                make_uint2(pack_bf16(kv.x - rb(kv.x), kv.y - rb(kv.y)),
                           pack_bf16(kv.z - rb(kv.z), kv.w - rb(kv.w)));
            float4 vv = *(const float4*)(Vt + row * DEPTH + c4);
            vstage[row * 68 + c4 + 0] = vv.x;
            vstage[row * 68 + c4 + 1] = vv.y;
            vstage[row * 68 + c4 + 2] = vv.z;
            vstage[row * 68 + c4 + 3] = vv.w;
        }
        __syncthreads();   // (b) K bf16 + vstage ready

        // ---- transpose V: staging -> VT[depth][keys] bf16 hi/lo ----
#pragma unroll
        for (int i = 0; i < 8; i++) {
            int key = vkg * 16 + i * 2;
            float v0 = vstage[key * 68 + vd];
            float v1 = vstage[(key + 1) * 68 + vd];
            *(uint32_t*)(smem + AVTHI + vd * AROWB + key * 2) = pack_bf16(v0, v1);
            *(uint32_t*)(smem + AVTLO + vd * AROWB + key * 2) =
                pack_bf16(v0 - rb(v0), v1 - rb(v1));
        }

        // ---- scores: s(16x64) = Qhi*Khi + Qhi*Klo + Qlo*Khi ----
        float s[8][4];
#pragma unroll
        for (int fn = 0; fn < 8; fn++)
#pragma unroll
            for (int e = 0; e < 4; e++) s[fn][e] = 0.f;

#pragma unroll
        for (int ks = 0; ks < 4; ks++) {
            uint32_t qh[4], ql[4];
            LDSM4(qh, qbase + AQHI + ks * 32);
            LDSM4(ql, qbase + AQLO + ks * 32);
            uint32_t kh[4][4], kl[4][4];
#pragma unroll
            for (int p = 0; p < 4; p++) {
                LDSM4(kh[p], bbase + AKHI + p * (16 * AROWB) + ks * 32);
                LDSM4(kl[p], bbase + AKLO + p * (16 * AROWB) + ks * 32);
            }
#pragma unroll
            for (int fn = 0; fn < 8; fn++) {
                const int p = fn >> 1, o2 = (fn & 1) << 1;
                MMA16816(s[fn], qh, kh[p][o2], kh[p][o2 + 1]);
                MMA16816(s[fn], qh, kl[p][o2], kl[p][o2 + 1]);
                MMA16816(s[fn], ql, kh[p][o2], kh[p][o2 + 1]);
            }
        }

        // ---- online softmax (rows r1=lid>>2, r2=r1+8; quad reduction) ----
        float mx1 = -1e30f, mx2 = -1e30f;
#pragma unroll
        for (int fn = 0; fn < 8; fn++) {
            mx1 = fmaxf(mx1, fmaxf(s[fn][0], s[fn][1]));
            mx2 = fmaxf(mx2, fmaxf(s[fn][2], s[fn][3]));
        }
        mx1 = fmaxf(mx1, __shfl_xor_sync(0xffffffffu, mx1, 1));
        mx1 = fmaxf(mx1, __shfl_xor_sync(0xffffffffu, mx1, 2));
        mx2 = fmaxf(mx2, __shfl_xor_sync(0xffffffffu, mx2, 1));
        mx2 = fmaxf(mx2, __shfl_xor_sync(0xffffffffu, mx2, 2));

        float mn1 = fmaxf(m1, mx1), mn2 = fmaxf(m2, mx2);
        float c1 = __expf(m1 - mn1), c2 = __expf(m2 - mn2);
        m1 = mn1; m2 = mn2;

        float rs1 = 0.f, rs2 = 0.f;
#pragma unroll
        for (int fn = 0; fn < 8; fn++) {
            s[fn][0] = __expf(s[fn][0] - m1);
            s[fn][1] = __expf(s[fn][1] - m1);
            s[fn][2] = __expf(s[fn][2] - m2);
            s[fn][3] = __expf(s[fn][3] - m2);
            rs1 += s[fn][0] + s[fn][1];
            rs2 += s[fn][2] + s[fn][3];
        }
        rs1 += __shfl_xor_sync(0xffffffffu, rs1, 1);
        rs1 += __shfl_xor_sync(0xffffffffu, rs1, 2);
        rs2 += __shfl_xor_sync(0xffffffffu, rs2, 1);
        rs2 += __shfl_xor_sync(0xffffffffu, rs2, 2);
        l1 = l1 * c1 + rs1;
        l2 = l2 * c2 + rs2;
#pragma unroll
        for (int fn = 0; fn < 8; fn++) {
            o[fn][0] *= c1; o[fn][1] *= c1;
            o[fn][2] *= c2; o[fn][3] *= c2;
        }
        __syncthreads();   // (c) VT writes visible to all warps

        // ---- O += P @ V : Phi*Vhi + Phi*Vlo + Plo*Vhi ----
#pragma unroll
        for (int ks = 0; ks < 4; ks++) {
            uint32_t pah[4], pal[4];
            {
                float p0 = s[2 * ks][0],     p1 = s[2 * ks][1];
                float p2 = s[2 * ks][2],     p3 = s[2 * ks][3];
                float p4 = s[2 * ks + 1][0], p5 = s[2 * ks + 1][1];
                float p6 = s[2 * ks + 1][2], p7 = s[2 * ks + 1][3];
                pah[0] = pack_bf16(p0, p1);  pah[1] = pack_bf16(p2, p3);
                pah[2] = pack_bf16(p4, p5);  pah[3] = pack_bf16(p6, p7);
                pal[0] = pack_bf16(p0 - rb(p0), p1 - rb(p1));
                pal[1] = pack_bf16(p2 - rb(p2), p3 - rb(p3));
                pal[2] = pack_bf16(p4 - rb(p4), p5 - rb(p5));
                pal[3] = pack_bf16(p6 - rb(p6), p7 - rb(p7));
            }
            uint32_t vh[4][4], vl[4][4];
#pragma unroll
            for (int p = 0; p < 4; p++) {
                LDSM4(vh[p], bbase + AVTHI + p * (16 * AROWB) + ks * 32);
                LDSM4(vl[p], bbase + AVTLO + p * (16 * AROWB) + ks * 32);
            }
#pragma unroll
            for (int fn = 0; fn < 8; fn++) {
                const int p = fn >> 1, o2 = (fn & 1) << 1;
                MMA16816(o[fn], pah, vh[p][o2], vh[p][o2 + 1]);
                MMA16816(o[fn], pah, vl[p][o2], vl[p][o2 + 1]);
                MMA16816(o[fn], pal, vh[p][o2], vh[p][o2 + 1]);
            }
        }
    }

    // ---- epilogue: normalize, store ----
    float inv1 = 1.f / l1, inv2 = 1.f / l2;
    int qr1 = wid * 16 + (lid >> 2);
    int qr2 = qr1 + 8;
#pragma unroll
    for (int fn = 0; fn < 8; fn++) {
        int col = fn * 8 + (lid & 3) * 2;
        *(float2*)(Op + qr1 * DEPTH + col) =
            make_float2(o[fn][0] * inv1, o[fn][1] * inv1);
        *(float2*)(Op + qr2 * DEPTH + col) =
            make_float2(o[fn][2] * inv2, o[fn][3] * inv2);
    }
}

// ---------------------------------------------------------------------------
extern "C" void kernel_launch(void* const* d_in, const int* in_sizes, int n_in,
                              void* d_out, int out_size)
{
    const float* q  = (const float*)d_in[0];
    const float* k  = (const float*)d_in[1];
    const float* v  = (const float*)d_in[2];
    const float* wq = (const float*)d_in[3];
    const float* bq = (const float*)d_in[4];
    const float* wk = (const float*)d_in[5];
    const float* bk = (const float*)d_in[6];
    const float* wv = (const float*)d_in[7];
    const float* bv = (const float*)d_in[8];
    const float* wo = (const float*)d_in[9];
    const float* bo = (const float*)d_in[10];
    float* out = (float*)d_out;

    float *gQ, *gK, *gV, *gO;
    cudaGetSymbolAddress((void**)&gQ, g_Q);
    cudaGetSymbolAddress((void**)&gK, g_K);
    cudaGetSymbolAddress((void**)&gV, g_V);
    cudaGetSymbolAddress((void**)&gO, g_O);

    cudaFuncSetAttribute(gemm_mma<false, true>,
                         cudaFuncAttributeMaxDynamicSharedMemorySize, GEMM_SMEM);
    cudaFuncSetAttribute(gemm_mma<true, false>,
                         cudaFuncAttributeMaxDynamicSharedMemorySize, GEMM_SMEM);
    cudaFuncSetAttribute(attn_mma,
                         cudaFuncAttributeMaxDynamicSharedMemorySize, ATT_SMEM);

    dim3 gproj(MTOT / 128, DM / 128);  // (32, 8)

    gemm_mma<false, true><<<gproj, 256, GEMM_SMEM>>>(q, wq, bq, gQ);
    gemm_mma<false, true><<<gproj, 256, GEMM_SMEM>>>(k, wk, bk, gK);
    gemm_mma<false, true><<<gproj, 256, GEMM_SMEM>>>(v, wv, bv, gV);

    attn_mma<<<dim3(SEQ / 128, NH, BATCH), 256, ATT_SMEM>>>(gQ, gK, gV, gO);

    gemm_mma<true, false><<<gproj, 256, GEMM_SMEM>>>(gO, wo, bo, out);
}

// round 7
// speedup vs baseline: 3.8770x; 1.0799x over previous
#include <cuda_runtime.h>
#include <cuda_bf16.h>
#include <cstdint>
#include <math.h>

#define BATCH 2
#define SEQ   2048
#define DM    1024
#define NH    16
#define DEPTH 64
#define MTOT  (BATCH*SEQ)   // 4096

#define QSCALE 0.1803368801111204f   // 0.125 * log2(e): scores in log2 domain

// Scratch: pre-split bf16 activations (hi/lo), head layouts
__device__ __nv_bfloat16 g_Qhi[BATCH*NH*SEQ*DEPTH];  // [B,H,S,D], pre-scaled
__device__ __nv_bfloat16 g_Qlo[BATCH*NH*SEQ*DEPTH];
__device__ __nv_bfloat16 g_Khi[BATCH*NH*SEQ*DEPTH];  // [B,H,S,D]
__device__ __nv_bfloat16 g_Klo[BATCH*NH*SEQ*DEPTH];
__device__ __nv_bfloat16 g_VThi[BATCH*NH*DEPTH*SEQ]; // [B,H,D,S] (transposed)
__device__ __nv_bfloat16 g_VTlo[BATCH*NH*DEPTH*SEQ];
__device__ float g_O[BATCH*NH*SEQ*DEPTH];            // attn out, fp32

// ===========================================================================
// helpers
// ===========================================================================
__device__ __forceinline__ uint32_t smem_u32(const void* p) {
    uint32_t a;
    asm("{ .reg .u64 t; cvta.to.shared.u64 t, %1; cvt.u32.u64 %0, t; }"
        : "=r"(a) : "l"(p));
    return a;
}
__device__ __forceinline__ uint32_t pack_bf16(float x, float y) {
    uint32_t lo = __bfloat16_as_ushort(__float2bfloat16(x));
    uint32_t hi = __bfloat16_as_ushort(__float2bfloat16(y));
    return lo | (hi << 16);
}
__device__ __forceinline__ float rb(float x) {
    return __bfloat162float(__float2bfloat16(x));
}
__device__ __forceinline__ float ex2(float x) {
    float y; asm("ex2.approx.ftz.f32 %0, %1;" : "=f"(y) : "f"(x)); return y;
}

#define LDSM4(R, addr) \
    asm volatile("ldmatrix.sync.aligned.m8n8.x4.shared.b16 {%0,%1,%2,%3}, [%4];" \
        : "=r"((R)[0]), "=r"((R)[1]), "=r"((R)[2]), "=r"((R)[3]) : "r"(addr))

#define MMA16816(D, A, B0, B1) \
    asm volatile("mma.sync.aligned.m16n8k16.row.col.f32.bf16.bf16.f32 " \
        "{%0,%1,%2,%3}, {%4,%5,%6,%7}, {%8,%9}, {%0,%1,%2,%3};" \
        : "+f"((D)[0]), "+f"((D)[1]), "+f"((D)[2]), "+f"((D)[3]) \
        : "r"((A)[0]), "r"((A)[1]), "r"((A)[2]), "r"((A)[3]), "r"(B0), "r"(B1))

#define CP16(dst, src) \
    asm volatile("cp.async.cg.shared.global [%0], [%1], 16;" \
        :: "r"(dst), "l"(src) : "memory")
#define CP_COMMIT()  asm volatile("cp.async.commit_group;" ::: "memory")
#define CP_WAIT1()   asm volatile("cp.async.wait_group 1;" ::: "memory")
#define CP_WAIT0()   asm volatile("cp.async.wait_group 0;" ::: "memory")

// ===========================================================================
// Split-bf16 tensor-core GEMM: C = A @ W.T + bias, then scaled + emitted per
// OMODE: 0 = fp32 [M,N];  1 = bf16 hi/lo [B,H,S,D];  2 = bf16 hi/lo [B,H,D,S].
// 2 CTAs/SM.
// ===========================================================================
#define ROWB 80
#define MAT_BYTES (128 * ROWB)
#define OFF_AHI 0
#define OFF_ALO (MAT_BYTES)
#define OFF_BHI (2 * MAT_BYTES)
#define OFF_BLO (3 * MAT_BYTES)
#define GSTG_A  (4 * MAT_BYTES)
#define GSTG_W  (GSTG_A + 2 * 16384)
#define GEMM_SMEM (GSTG_W + 2 * 16384)  // 106496

template<bool GATHER_A, int OMODE>
__global__ __launch_bounds__(256, 2)
void gemm_mma(const float* __restrict__ A, const float* __restrict__ W,
              const float* __restrict__ bias, float* __restrict__ C32,
              __nv_bfloat16* __restrict__ Chi, __nv_bfloat16* __restrict__ Clo,
              float scale)
{
    extern __shared__ char smem[];
    const uint32_t sb = smem_u32(smem);

    const int tid = threadIdx.x;
    const int wid = tid >> 5, lid = tid & 31;
    const int warp_m = wid >> 2;
    const int warp_n = wid & 3;
    const int bm = blockIdx.x * 128, bn = blockIdx.y * 128;

    const int grp = lid >> 3, r = lid & 7;
    const uint32_t a_base = sb + OFF_AHI
        + (uint32_t)(warp_m * 64 + ((grp & 1) << 3) + r) * ROWB
        + (uint32_t)(((grp >> 1) & 1) << 4);
    const uint32_t b_base = sb + OFF_BHI
        + (uint32_t)(warp_n * 32 + (((grp >> 1) & 1) << 3) + r) * ROWB
        + (uint32_t)((grp & 1) << 4);

    auto issue_tile = [&](int it) {
        const int k0 = it * 32;
        const uint32_t buf = (uint32_t)(it & 1) * 16384u;
#pragma unroll
        for (int l = 0; l < 4; l++) {
            int idx = tid + l * 256;
            int row = idx >> 3;
            int cf  = (idx & 7) << 2;
            uint32_t doff = (uint32_t)row * 128 + (uint32_t)cf * 4;
            const float* srcA;
            if (GATHER_A) {
                int m = bm + row;
                int b = m >> 11, s = m & 2047;
                int h = it >> 1, dl = ((it & 1) << 5) + cf;
                srcA = A + ((((b << 4) + h) * SEQ + s) << 6) + dl;
            } else {
                srcA = A + (size_t)(bm + row) * DM + k0 + cf;
            }
            CP16(sb + GSTG_A + buf + doff, srcA);
            CP16(sb + GSTG_W + buf + doff,
                 W + (size_t)(bn + row) * DM + k0 + cf);
        }
    };

    float acc[4][4][4];
#pragma unroll
    for (int i = 0; i < 4; i++)
#pragma unroll
        for (int j = 0; j < 4; j++)
#pragma unroll
            for (int e = 0; e < 4; e++) acc[i][j][e] = 0.f;

    issue_tile(0);
    CP_COMMIT();

    for (int it = 0; it < DM / 32; it++) {
        if (it + 1 < DM / 32) issue_tile(it + 1);
        CP_COMMIT();
        CP_WAIT1();
        __syncthreads();

        const float* stA = (const float*)(smem + GSTG_A + (it & 1) * 16384);
        const float* stW = (const float*)(smem + GSTG_W + (it & 1) * 16384);
#pragma unroll
        for (int l = 0; l < 4; l++) {
            int idx = tid + l * 256;
            int row = idx >> 3;
            int cf  = (idx & 7) << 2;
            uint32_t soff = (uint32_t)row * ROWB + (uint32_t)cf * 2;
            float4 va = *(const float4*)(stA + row * 32 + cf);
            *(uint2*)(smem + OFF_AHI + soff) =
                make_uint2(pack_bf16(va.x, va.y), pack_bf16(va.z, va.w));
            *(uint2*)(smem + OFF_ALO + soff) =
                make_uint2(pack_bf16(va.x - rb(va.x), va.y - rb(va.y)),
                           pack_bf16(va.z - rb(va.z), va.w - rb(va.w)));
            float4 vw = *(const float4*)(stW + row * 32 + cf);
            *(uint2*)(smem + OFF_BHI + soff) =
                make_uint2(pack_bf16(vw.x, vw.y), pack_bf16(vw.z, vw.w));
            *(uint2*)(smem + OFF_BLO + soff) =
                make_uint2(pack_bf16(vw.x - rb(vw.x), vw.y - rb(vw.y)),
                           pack_bf16(vw.z - rb(vw.z), vw.w - rb(vw.w)));
        }
        __syncthreads();

#pragma unroll
        for (int ks = 0; ks < 2; ks++) {
            const uint32_t offk = (uint32_t)ks * 32;
            uint32_t ah[4][4], al[4][4], bh[2][4], bl[2][4];
#pragma unroll
            for (int fm = 0; fm < 4; fm++) {
                LDSM4(ah[fm], a_base + fm * (16 * ROWB) + offk);
                LDSM4(al[fm], a_base + (OFF_ALO - OFF_AHI) + fm * (16 * ROWB) + offk);
            }
#pragma unroll
            for (int p = 0; p < 2; p++) {
                LDSM4(bh[p], b_base + p * (16 * ROWB) + offk);
                LDSM4(bl[p], b_base + (OFF_BLO - OFF_BHI) + p * (16 * ROWB) + offk);
            }
#pragma unroll
            for (int fm = 0; fm < 4; fm++)
#pragma unroll
                for (int fn = 0; fn < 4; fn++) {
                    const int p = fn >> 1, o = (fn & 1) << 1;
                    MMA16816(acc[fm][fn], ah[fm], bh[p][o], bh[p][o + 1]);
                    MMA16816(acc[fm][fn], ah[fm], bl[p][o], bl[p][o + 1]);
                    MMA16816(acc[fm][fn], al[fm], bh[p][o], bh[p][o + 1]);
                }
        }
    }

    const int qrow = lid >> 2;
    const int qcol = (lid & 3) << 1;
#pragma unroll
    for (int fm = 0; fm < 4; fm++) {
        int m1 = bm + warp_m * 64 + fm * 16 + qrow;
        int m2 = m1 + 8;
#pragma unroll
        for (int fn = 0; fn < 4; fn++) {
            int n = bn + warp_n * 32 + fn * 8 + qcol;
            float2 bb = *(const float2*)(bias + n);
            float x1 = (acc[fm][fn][0] + bb.x) * scale;
            float y1 = (acc[fm][fn][1] + bb.y) * scale;
            float x2 = (acc[fm][fn][2] + bb.x) * scale;
            float y2 = (acc[fm][fn][3] + bb.y) * scale;
            if (OMODE == 0) {
                *(float2*)(C32 + (size_t)m1 * DM + n) = make_float2(x1, y1);
                *(float2*)(C32 + (size_t)m2 * DM + n) = make_float2(x2, y2);
            } else {
                int h = n >> 6, dl = n & 63;
                int b1 = m1 >> 11, s1 = m1 & 2047;
                int b2 = m2 >> 11, s2 = m2 & 2047;
                if (OMODE == 1) {
                    size_t i1 = (size_t)((((b1 << 4) + h) * SEQ + s1) << 6) + dl;
                    size_t i2 = (size_t)((((b2 << 4) + h) * SEQ + s2) << 6) + dl;
                    *(uint32_t*)(Chi + i1) = pack_bf16(x1, y1);
                    *(uint32_t*)(Clo + i1) = pack_bf16(x1 - rb(x1), y1 - rb(y1));
                    *(uint32_t*)(Chi + i2) = pack_bf16(x2, y2);
                    *(uint32_t*)(Clo + i2) = pack_bf16(x2 - rb(x2), y2 - rb(y2));
                } else {
                    // transposed: [B,H,D,S]
                    size_t t1 = ((size_t)((b1 << 4) + h) * 64 + dl) * SEQ + s1;
                    size_t t2 = ((size_t)((b2 << 4) + h) * 64 + dl) * SEQ + s2;
                    Chi[t1] = __float2bfloat16(x1);
                    Clo[t1] = __float2bfloat16(x1 - rb(x1));
                    Chi[t1 + SEQ] = __float2bfloat16(y1);
                    Clo[t1 + SEQ] = __float2bfloat16(y1 - rb(y1));
                    Chi[t2] = __float2bfloat16(x2);
                    Clo[t2] = __float2bfloat16(x2 - rb(x2));
                    Chi[t2 + SEQ] = __float2bfloat16(y2);
                    Clo[t2 + SEQ] = __float2bfloat16(y2 - rb(y2));
                }
            }
        }
    }
}

// ===========================================================================
// Tensor-core flash attention. All operands pre-split bf16 in gmem.
// cp.async straight into ldmatrix layout; double-buffered K/VT; ONE barrier
// per iteration; log2-domain softmax (ex2). 2 CTAs/SM.
// ===========================================================================
#define AROWB 144
#define AQHI  0                    // Q hi: 128 x 144
#define AQLO  18432
#define ABUF  36864                // two K/VT buffers of 36864 each
// within a buffer: Khi +0, Klo +9216, VThi +18432, VTlo +27648 (= mat*9216)
#define ATT_SMEM (ABUF + 2 * 36864)   // 110592 -> 2 CTAs/SM

__global__ __launch_bounds__(256, 2)
void attn_mma(const __nv_bfloat16* __restrict__ Qhi,
              const __nv_bfloat16* __restrict__ Qlo,
              const __nv_bfloat16* __restrict__ Khi,
              const __nv_bfloat16* __restrict__ Klo,
              const __nv_bfloat16* __restrict__ VThi,
              const __nv_bfloat16* __restrict__ VTlo,
              float* __restrict__ O)
{
    extern __shared__ char smem[];
    const uint32_t sb = smem_u32(smem);
    const int tid = threadIdx.x, wid = tid >> 5, lid = tid & 31;
    const int grp = lid >> 3, r = lid & 7;

    const int bh = blockIdx.z * NH + blockIdx.y;
    const int q0 = blockIdx.x * 128;
    const __nv_bfloat16* Qhp = Qhi + (size_t)(bh * SEQ + q0) * DEPTH;
    const __nv_bfloat16* Qlp = Qlo + (size_t)(bh * SEQ + q0) * DEPTH;
    const __nv_bfloat16* Khp = Khi + (size_t)bh * SEQ * DEPTH;
    const __nv_bfloat16* Klp = Klo + (size_t)bh * SEQ * DEPTH;
    const __nv_bfloat16* Vhp = VThi + (size_t)bh * DEPTH * SEQ;
    const __nv_bfloat16* Vlp = VTlo + (size_t)bh * DEPTH * SEQ;
    float* Op = O + (size_t)(bh * SEQ + q0) * DEPTH;

    const int crow = tid >> 3;     // 0..31 within a 32-row chunk group
    const int cch  = tid & 7;      // 16B chunk in row

    auto issue_tile = [&](int kt) {
        const uint32_t buf = sb + ABUF + (uint32_t)(kt & 1) * 36864u;
        const int s0 = kt * 64;
#pragma unroll
        for (int l = 0; l < 8; l++) {
            int mat = l >> 1;                       // 0 Khi,1 Klo,2 VThi,3 VTlo
            int row = ((l & 1) << 5) + crow;        // 0..63
            uint32_t dst = buf + (uint32_t)mat * 9216u
                         + (uint32_t)row * AROWB + (uint32_t)cch * 16;
            const __nv_bfloat16* src;
            if (mat == 0)      src = Khp + (size_t)(s0 + row) * DEPTH + cch * 8;
            else if (mat == 1) src = Klp + (size_t)(s0 + row) * DEPTH + cch * 8;
            else if (mat == 2) src = Vhp + (size_t)row * SEQ + s0 + cch * 8;
            else               src = Vlp + (size_t)row * SEQ + s0 + cch * 8;
            CP16(dst, src);
        }
    };

    // prologue: Q (persistent) + tile 0, one group
#pragma unroll
    for (int l = 0; l < 8; l++) {
        int mat = l >> 2;                           // 0 Qhi, 1 Qlo
        int row = ((l & 3) << 5) + crow;            // 0..127
        uint32_t dst = sb + (uint32_t)mat * 18432u
                     + (uint32_t)row * AROWB + (uint32_t)cch * 16;
        const __nv_bfloat16* src = (mat == 0 ? Qhp : Qlp)
                                 + (size_t)row * DEPTH + cch * 8;
        CP16(dst, src);
    }
    issue_tile(0);
    CP_COMMIT();

    const uint32_t qbase = sb + (uint32_t)(wid * 16 + ((grp & 1) << 3) + r) * AROWB
                         + (uint32_t)(((grp >> 1) & 1) << 4);
    const uint32_t bpat  = (uint32_t)(((grp & 2) << 2) + r) * AROWB
                         + (uint32_t)((grp & 1) << 4);

    float o[8][4];
#pragma unroll
    for (int fn = 0; fn < 8; fn++)
#pragma unroll
        for (int e = 0; e < 4; e++) o[fn][e] = 0.f;
    float m1 = -1e30f, m2 = -1e30f, l1 = 0.f, l2 = 0.f;

    for (int kt = 0; kt < SEQ / 64; kt++) {
        CP_WAIT0();
        __syncthreads();   // buf[kt&1] (+Q at kt=0) visible; prev-iter reads done
        if (kt + 1 < SEQ / 64) { issue_tile(kt + 1); CP_COMMIT(); }

        const uint32_t kvb = sb + ABUF + (uint32_t)(kt & 1) * 36864u + bpat;

        // ---- scores: s(16x64) = Qhi*Khi + Qhi*Klo + Qlo*Khi ----
        float s[8][4];
#pragma unroll
        for (int fn = 0; fn < 8; fn++)
#pragma unroll
            for (int e = 0; e < 4; e++) s[fn][e] = 0.f;

#pragma unroll
        for (int ks = 0; ks < 4; ks++) {
            uint32_t qh[4], ql[4];
            LDSM4(qh, qbase + AQHI + ks * 32);
            LDSM4(ql, qbase + AQLO + ks * 32);
            uint32_t kh[4][4], kl[4][4];
#pragma unroll
            for (int p = 0; p < 4; p++) {
                LDSM4(kh[p], kvb + p * (16 * AROWB) + ks * 32);
                LDSM4(kl[p], kvb + 9216 + p * (16 * AROWB) + ks * 32);
            }
#pragma unroll
            for (int fn = 0; fn < 8; fn++) {
                const int p = fn >> 1, o2 = (fn & 1) << 1;
                MMA16816(s[fn], qh, kh[p][o2], kh[p][o2 + 1]);
                MMA16816(s[fn], qh, kl[p][o2], kl[p][o2 + 1]);
                MMA16816(s[fn], ql, kh[p][o2], kh[p][o2 + 1]);
            }
        }

        // ---- online softmax in log2 domain ----
        float mx1 = -1e30f, mx2 = -1e30f;
#pragma unroll
        for (int fn = 0; fn < 8; fn++) {
            mx1 = fmaxf(mx1, fmaxf(s[fn][0], s[fn][1]));
            mx2 = fmaxf(mx2, fmaxf(s[fn][2], s[fn][3]));
        }
        mx1 = fmaxf(mx1, __shfl_xor_sync(0xffffffffu, mx1, 1));
        mx1 = fmaxf(mx1, __shfl_xor_sync(0xffffffffu, mx1, 2));
        mx2 = fmaxf(mx2, __shfl_xor_sync(0xffffffffu, mx2, 1));
        mx2 = fmaxf(mx2, __shfl_xor_sync(0xffffffffu, mx2, 2));

        float mn1 = fmaxf(m1, mx1), mn2 = fmaxf(m2, mx2);
        float c1 = ex2(m1 - mn1), c2 = ex2(m2 - mn2);
        m1 = mn1; m2 = mn2;

        float rs1 = 0.f, rs2 = 0.f;
#pragma unroll
        for (int fn = 0; fn < 8; fn++) {
            s[fn][0] = ex2(s[fn][0] - m1);
            s[fn][1] = ex2(s[fn][1] - m1);
            s[fn][2] = ex2(s[fn][2] - m2);
            s[fn][3] = ex2(s[fn][3] - m2);
            rs1 += s[fn][0] + s[fn][1];
            rs2 += s[fn][2] + s[fn][3];
        }
        rs1 += __shfl_xor_sync(0xffffffffu, rs1, 1);
        rs1 += __shfl_xor_sync(0xffffffffu, rs1, 2);
        rs2 += __shfl_xor_sync(0xffffffffu, rs2, 1);
        rs2 += __shfl_xor_sync(0xffffffffu, rs2, 2);
        l1 = l1 * c1 + rs1;
        l2 = l2 * c2 + rs2;
#pragma unroll
        for (int fn = 0; fn < 8; fn++) {
            o[fn][0] *= c1; o[fn][1] *= c1;
            o[fn][2] *= c2; o[fn][3] *= c2;
        }

        // ---- O += P @ V : Phi*Vhi + Phi*Vlo + Plo*Vhi ----
#pragma unroll
        for (int ks = 0; ks < 4; ks++) {
            uint32_t pah[4], pal[4];
            {
                float p0 = s[2 * ks][0],     p1 = s[2 * ks][1];
                float p2 = s[2 * ks][2],     p3 = s[2 * ks][3];
                float p4 = s[2 * ks + 1][0], p5 = s[2 * ks + 1][1];
                float p6 = s[2 * ks + 1][2], p7 = s[2 * ks + 1][3];
                pah[0] = pack_bf16(p0, p1);  pah[1] = pack_bf16(p2, p3);
                pah[2] = pack_bf16(p4, p5);  pah[3] = pack_bf16(p6, p7);
                pal[0] = pack_bf16(p0 - rb(p0), p1 - rb(p1));
                pal[1] = pack_bf16(p2 - rb(p2), p3 - rb(p3));
                pal[2] = pack_bf16(p4 - rb(p4), p5 - rb(p5));
                pal[3] = pack_bf16(p6 - rb(p6), p7 - rb(p7));
            }
            uint32_t vh[4][4], vl[4][4];
#pragma unroll
            for (int p = 0; p < 4; p++) {
                LDSM4(vh[p], kvb + 18432 + p * (16 * AROWB) + ks * 32);
                LDSM4(vl[p], kvb + 27648 + p * (16 * AROWB) + ks * 32);
            }
#pragma unroll
            for (int fn = 0; fn < 8; fn++) {
                const int p = fn >> 1, o2 = (fn & 1) << 1;
                MMA16816(o[fn], pah, vh[p][o2], vh[p][o2 + 1]);
                MMA16816(o[fn], pah, vl[p][o2], vl[p][o2 + 1]);
                MMA16816(o[fn], pal, vh[p][o2], vh[p][o2 + 1]);
            }
        }
    }

    // ---- epilogue: normalize, store fp32 ----
    float inv1 = 1.f / l1, inv2 = 1.f / l2;
    int qr1 = wid * 16 + (lid >> 2);
    int qr2 = qr1 + 8;
#pragma unroll
    for (int fn = 0; fn < 8; fn++) {
        int col = fn * 8 + (lid & 3) * 2;
        *(float2*)(Op + qr1 * DEPTH + col) =
            make_float2(o[fn][0] * inv1, o[fn][1] * inv1);
        *(float2*)(Op + qr2 * DEPTH + col) =
            make_float2(o[fn][2] * inv2, o[fn][3] * inv2);
    }
}

// ---------------------------------------------------------------------------
extern "C" void kernel_launch(void* const* d_in, const int* in_sizes, int n_in,
                              void* d_out, int out_size)
{
    const float* q  = (const float*)d_in[0];
    const float* k  = (const float*)d_in[1];
    const float* v  = (const float*)d_in[2];
    const float* wq = (const float*)d_in[3];
    const float* bq = (const float*)d_in[4];
    const float* wk = (const float*)d_in[5];
    const float* bk = (const float*)d_in[6];
    const float* wv = (const float*)d_in[7];
    const float* bv = (const float*)d_in[8];
    const float* wo = (const float*)d_in[9];
    const float* bo = (const float*)d_in[10];
    float* out = (float*)d_out;

    __nv_bfloat16 *gQh, *gQl, *gKh, *gKl, *gVh, *gVl;
    float *gO;
    cudaGetSymbolAddress((void**)&gQh, g_Qhi);
    cudaGetSymbolAddress((void**)&gQl, g_Qlo);
    cudaGetSymbolAddress((void**)&gKh, g_Khi);
    cudaGetSymbolAddress((void**)&gKl, g_Klo);
    cudaGetSymbolAddress((void**)&gVh, g_VThi);
    cudaGetSymbolAddress((void**)&gVl, g_VTlo);
    cudaGetSymbolAddress((void**)&gO,  g_O);

    cudaFuncSetAttribute(gemm_mma<false, 1>,
                         cudaFuncAttributeMaxDynamicSharedMemorySize, GEMM_SMEM);
    cudaFuncSetAttribute(gemm_mma<false, 2>,
                         cudaFuncAttributeMaxDynamicSharedMemorySize, GEMM_SMEM);
    cudaFuncSetAttribute(gemm_mma<true, 0>,
                         cudaFuncAttributeMaxDynamicSharedMemorySize, GEMM_SMEM);
    cudaFuncSetAttribute(attn_mma,
                         cudaFuncAttributeMaxDynamicSharedMemorySize, ATT_SMEM);

    dim3 gproj(MTOT / 128, DM / 128);  // (32, 8)

    gemm_mma<false, 1><<<gproj, 256, GEMM_SMEM>>>(q, wq, bq, nullptr, gQh, gQl,
                                                  QSCALE);
    gemm_mma<false, 1><<<gproj, 256, GEMM_SMEM>>>(k, wk, bk, nullptr, gKh, gKl,
                                                  1.0f);
    gemm_mma<false, 2><<<gproj, 256, GEMM_SMEM>>>(v, wv, bv, nullptr, gVh, gVl,
                                                  1.0f);

    attn_mma<<<dim3(SEQ / 128, NH, BATCH), 256, ATT_SMEM>>>(gQh, gQl, gKh, gKl,
                                                            gVh, gVl, gO);

    gemm_mma<true, 0><<<gproj, 256, GEMM_SMEM>>>(gO, wo, bo, out, nullptr,
                                                 nullptr, 1.0f);
}